// round 11
// baseline (speedup 1.0000x reference)
#include <cuda_runtime.h>
#include <cuda_bf16.h>

#define BATCH 8
#define NCPT 4096
#define NTPT 4096
#define NND  1024
#define NE   16384
#define HD   128
#define LNEPS 1e-5f
#define KSPLIT 8

typedef unsigned long long ull;

// ---------------- scratch (device globals; no allocation) ----------------
__device__ __align__(16) float g_tmpA[BATCH*NCPT*HD];   // reused as scatter partials [8][8192][128]
__device__ __align__(16) float g_tmpB[BATCH*NCPT*HD];
__device__ __align__(16) float g_emb [BATCH*NCPT*HD];
__device__ __align__(16) float g_q   [BATCH*NTPT*HD];
__device__ __align__(16) float g_z   [BATCH*NTPT*HD];
__device__ __align__(16) float g_latA[BATCH*NND*HD];
__device__ __align__(16) float g_latB[BATCH*NND*HD];
__device__ __align__(16) float g_NR  [BATCH*NND*HD];
__device__ __align__(16) float g_NS  [BATCH*NND*HD];
__device__ __align__(16) float g_inb [BATCH*NND*HD];
__device__ float g_alC[BATCH*NCPT];
__device__ float g_alT[BATCH*NTPT];
__device__ int   g_cnt[NND];
__device__ int   g_cur[NND];
__device__ int   g_off[NND+1];
__device__ int   g_csr[NE];

// ---------------- f32x2 helpers ----------------
__device__ __forceinline__ ull pk2(float a, float b){
    ull u; asm("mov.b64 %0,{%1,%2};" : "=l"(u) : "f"(a), "f"(b)); return u;
}
__device__ __forceinline__ void fma2(ull &c, ull a, ull b){
    asm("fma.rn.f32x2 %0,%1,%2,%0;" : "+l"(c) : "l"(a), "l"(b));
}
__device__ __forceinline__ float2 upk(ull u){
    float2 f; asm("mov.b64 {%0,%1},%2;" : "=f"(f.x), "=f"(f.y) : "l"(u)); return f;
}

#define AS_STRIDE 66

// ---------------- first MLP layer, tiny K (concat A1[d1] | A2[d2]) ----------------
__global__ void mlp_l1_kernel(const float* __restrict__ A1, int d1,
                              const float* __restrict__ A2, int d2,
                              const float* __restrict__ W0, const float* __restrict__ b0,
                              float* __restrict__ out)
{
    int row = blockIdx.x;
    int c   = threadIdx.x;
    float acc = b0[c];
    for (int k = 0; k < d1; k++) acc += A1[row*d1 + k] * W0[k*HD + c];
    for (int k = 0; k < d2; k++) acc += A2[row*d2 + k] * W0[(d1+k)*HD + c];
    out[row*HD + c] = fmaxf(acc, 0.f);
}

// ---------------- alpha for both point sets in one launch ----------------
__global__ void __launch_bounds__(256) alpha2_kernel(
    const float* __restrict__ XC, const float* __restrict__ XT,
    const float* __restrict__ pos, float* __restrict__ alC, float* __restrict__ alT)
{
    int row  = blockIdx.x*8 + (threadIdx.x >> 5);
    int lane = threadIdx.x & 31;
    const float* X; float* alpha; int r;
    if (row < BATCH*NCPT){ X = XC; alpha = alC; r = row; }
    else { X = XT; alpha = alT; r = row - BATCH*NCPT; }
    float2 x = reinterpret_cast<const float2*>(X)[r];
    float l[32];
    const float2* p2 = reinterpret_cast<const float2*>(pos);
    #pragma unroll
    for (int i = 0; i < 32; i++){
        float2 p = p2[i*32 + lane];
        l[i] = 2.f*(x.x*p.x + x.y*p.y) - (p.x*p.x + p.y*p.y);
    }
    float m = l[0];
    #pragma unroll
    for (int i = 1; i < 32; i++) m = fmaxf(m, l[i]);
    #pragma unroll
    for (int d = 1; d < 32; d <<= 1) m = fmaxf(m, __shfl_xor_sync(0xffffffffu, m, d));
    float s = 0.f;
    #pragma unroll
    for (int i = 0; i < 32; i++) s += __expf(l[i] - m);
    #pragma unroll
    for (int d = 1; d < 32; d <<= 1) s += __shfl_xor_sync(0xffffffffu, s, d);
    if (lane == 0) alpha[r] = -(m + logf(s));
}

// ==== row-pair f32x2 core: acc[rp][u] packs rows (ty*4+2rp, +1), col = 2*tx+32*(u>>1)+(u&1) ====
__device__ __forceinline__ void mma_rows4(ull acc[2][8], const float* As, const ull* Ws2,
                                          int ty, int tx)
{
    #pragma unroll
    for (int k = 0; k < 32; k++){
        ulonglong2 wv[4];
        #pragma unroll
        for (int j = 0; j < 4; j++)
            wv[j] = *reinterpret_cast<const ulonglong2*>(&Ws2[k*HD + 2*tx + 32*j]);
        ull a01 = *reinterpret_cast<const ull*>(&As[k*AS_STRIDE + ty*4]);
        ull a23 = *reinterpret_cast<const ull*>(&As[k*AS_STRIDE + ty*4 + 2]);
        #pragma unroll
        for (int j = 0; j < 4; j++){
            fma2(acc[0][2*j],   a01, wv[j].x);
            fma2(acc[0][2*j+1], a01, wv[j].y);
            fma2(acc[1][2*j],   a23, wv[j].x);
            fma2(acc[1][2*j+1], a23, wv[j].y);
        }
    }
}

// ---------------- generic [M,K]@[K,128] GEMM, K in {128,256} (A = A1|A2 concat) ----------------
// EPI: 1=bias, 2=bias+relu, 3=bias+LayerNorm(g,bet)
template<int EPI>
__global__ void __launch_bounds__(256) gemm128_kernel(
    const float* __restrict__ A1, const float* __restrict__ A2,
    const float* __restrict__ W,  const float* __restrict__ bias,
    const float* __restrict__ g,  const float* __restrict__ bet,
    float* __restrict__ out, int K)
{
    __shared__ __align__(16) float As[32*AS_STRIDE];
    __shared__ __align__(16) ull   Ws2[32*HD];
    int tid = threadIdx.x;
    int tx = tid & 15, ty = tid >> 4;
    int row0 = blockIdx.x * 64;

    ull acc[2][8];
    #pragma unroll
    for (int r = 0; r < 2; r++)
        #pragma unroll
        for (int j = 0; j < 8; j++) acc[r][j] = 0ULL;

    int nch = K >> 5;
    for (int cc = 0; cc < nch; cc++){
        int kg = cc << 5;
        const float* Asrc = (kg < 128) ? A1 : A2;
        int koff = (kg < 128) ? kg : kg - 128;
        __syncthreads();
        #pragma unroll
        for (int i = 0; i < 8; i++){
            int e = tid + i*256;
            int m = e >> 5, k = e & 31;
            As[k*AS_STRIDE + m] = Asrc[(row0 + m)*HD + koff + k];
        }
        #pragma unroll
        for (int i = 0; i < 16; i++){
            int e = tid + i*256;
            float w = W[kg*HD + e];
            Ws2[e] = pk2(w, w);
        }
        __syncthreads();
        mma_rows4(acc, As, Ws2, ty, tx);
    }

    float bv[8];
    #pragma unroll
    for (int j = 0; j < 4; j++){
        bv[2*j]   = bias[2*tx + 32*j];
        bv[2*j+1] = bias[2*tx + 32*j + 1];
    }
    #pragma unroll
    for (int r = 0; r < 4; r++){
        int rp = r >> 1, s = r & 1;
        int row = row0 + ty*4 + r;
        float v[8];
        #pragma unroll
        for (int u = 0; u < 8; u++){
            float2 pu = upk(acc[rp][u]);
            v[u] = (s ? pu.y : pu.x) + bv[u];
        }
        if (EPI == 2){
            #pragma unroll
            for (int u = 0; u < 8; u++) v[u] = fmaxf(v[u], 0.f);
        }
        if (EPI == 3){
            float sm = 0.f, s2 = 0.f;
            #pragma unroll
            for (int u = 0; u < 8; u++){ sm += v[u]; s2 += v[u]*v[u]; }
            #pragma unroll
            for (int d = 1; d < 16; d <<= 1){
                sm += __shfl_xor_sync(0xffffffffu, sm, d);
                s2 += __shfl_xor_sync(0xffffffffu, s2, d);
            }
            float mu = sm * (1.f/HD);
            float rs = rsqrtf(s2 * (1.f/HD) - mu*mu + LNEPS);
            #pragma unroll
            for (int j = 0; j < 4; j++){
                int c = 2*tx + 32*j;
                v[2*j]   = (v[2*j]   - mu) * rs * g[c]   + bet[c];
                v[2*j+1] = (v[2*j+1] - mu) * rs * g[c+1] + bet[c+1];
            }
        }
        #pragma unroll
        for (int j = 0; j < 4; j++){
            float2 o; o.x = v[2*j]; o.y = v[2*j+1];
            *reinterpret_cast<float2*>(&out[row*HD + 2*tx + 32*j]) = o;
        }
    }
}

// ---------------- merged message GEMM: NR = A@WR + bR, NS = A@WS (K=128) ----------------
// One A-load per chunk; two W passes through the same Ws2 buffer.
__global__ void __launch_bounds__(256) gemm_msg_kernel(
    const float* __restrict__ A,
    const float* __restrict__ WR, const float* __restrict__ WS,
    const float* __restrict__ bR,
    float* __restrict__ outR, float* __restrict__ outS)
{
    __shared__ __align__(16) float As[32*AS_STRIDE];
    __shared__ __align__(16) ull   Ws2[32*HD];
    int tid = threadIdx.x;
    int tx = tid & 15, ty = tid >> 4;
    int row0 = blockIdx.x * 64;

    ull accR[2][8], accS[2][8];
    #pragma unroll
    for (int r = 0; r < 2; r++)
        #pragma unroll
        for (int j = 0; j < 8; j++){ accR[r][j] = 0ULL; accS[r][j] = 0ULL; }

    for (int cc = 0; cc < 4; cc++){
        int kg = cc << 5;
        __syncthreads();
        #pragma unroll
        for (int i = 0; i < 8; i++){
            int e = tid + i*256;
            int m = e >> 5, k = e & 31;
            As[k*AS_STRIDE + m] = A[(row0 + m)*HD + kg + k];
        }
        #pragma unroll
        for (int i = 0; i < 16; i++){
            int e = tid + i*256;
            float w = WR[kg*HD + e];
            Ws2[e] = pk2(w, w);
        }
        __syncthreads();
        mma_rows4(accR, As, Ws2, ty, tx);
        __syncthreads();
        #pragma unroll
        for (int i = 0; i < 16; i++){
            int e = tid + i*256;
            float w = WS[kg*HD + e];
            Ws2[e] = pk2(w, w);
        }
        __syncthreads();
        mma_rows4(accS, As, Ws2, ty, tx);
    }

    float bv[8];
    #pragma unroll
    for (int j = 0; j < 4; j++){
        bv[2*j]   = bR[2*tx + 32*j];
        bv[2*j+1] = bR[2*tx + 32*j + 1];
    }
    #pragma unroll
    for (int r = 0; r < 4; r++){
        int rp = r >> 1, s = r & 1;
        int row = row0 + ty*4 + r;
        #pragma unroll
        for (int j = 0; j < 4; j++){
            float2 p0 = upk(accR[rp][2*j]);
            float2 p1 = upk(accR[rp][2*j+1]);
            float2 o; o.x = (s ? p0.y : p0.x) + bv[2*j]; o.y = (s ? p1.y : p1.x) + bv[2*j+1];
            *reinterpret_cast<float2*>(&outR[row*HD + 2*tx + 32*j]) = o;
            float2 q0 = upk(accS[rp][2*j]);
            float2 q1 = upk(accS[rp][2*j+1]);
            float2 u; u.x = (s ? q0.y : q0.x); u.y = (s ? q1.y : q1.x);
            *reinterpret_cast<float2*>(&outS[row*HD + 2*tx + 32*j]) = u;
        }
    }
}

// ---------------- scatter partials: 64 nodes/CTA, KSPLIT chunks over contexts ----------------
__global__ void __launch_bounds__(256) scatter_kernel(
    const float* __restrict__ xc, const float* __restrict__ pos,
    const float* __restrict__ alpha, const float* __restrict__ emb,
    float* __restrict__ part)
{
    __shared__ __align__(16) float Ss[32*AS_STRIDE];   // [c-local][node-local]
    __shared__ __align__(16) ull   Es2[32*HD];
    __shared__ float spx[64], spy[64], spn[64];
    int tid = threadIdx.x;
    int tx = tid & 15, ty = tid >> 4;
    int b = blockIdx.y, n0 = blockIdx.x*64;
    int z = blockIdx.z;

    if (tid < 64){
        float2 p = reinterpret_cast<const float2*>(pos)[n0 + tid];
        spx[tid] = p.x; spy[tid] = p.y; spn[tid] = p.x*p.x + p.y*p.y;
    }
    ull acc[2][8];
    #pragma unroll
    for (int r = 0; r < 2; r++)
        #pragma unroll
        for (int j = 0; j < 8; j++) acc[r][j] = 0ULL;

    int cbeg = z * (NCPT/KSPLIT);
    int cend = cbeg + (NCPT/KSPLIT);
    for (int cc = cbeg; cc < cend; cc += 32){
        __syncthreads();
        #pragma unroll
        for (int i = 0; i < 16; i++){
            int e = tid + i*256;
            float w = emb[(b*NCPT + cc)*HD + e];
            Es2[e] = pk2(w, w);
        }
        #pragma unroll
        for (int i = 0; i < 8; i++){
            int e = tid + i*256;
            int c = e >> 6, nl = e & 63;
            int crow = b*NCPT + cc + c;
            float2 x = reinterpret_cast<const float2*>(xc)[crow];
            Ss[c*AS_STRIDE + nl] = __expf(2.f*(x.x*spx[nl] + x.y*spy[nl]) - spn[nl] + alpha[crow]);
        }
        __syncthreads();
        mma_rows4(acc, Ss, Es2, ty, tx);
    }
    int zoff = z * (BATCH*NND*HD);
    #pragma unroll
    for (int r = 0; r < 4; r++){
        int rp = r >> 1, s = r & 1;
        int row = b*NND + n0 + ty*4 + r;
        #pragma unroll
        for (int j = 0; j < 4; j++){
            float2 p0 = upk(acc[rp][2*j]);
            float2 p1 = upk(acc[rp][2*j+1]);
            float2 o; o.x = (s ? p0.y : p0.x); o.y = (s ? p1.y : p1.x);
            *reinterpret_cast<float2*>(&part[zoff + row*HD + 2*tx + 32*j]) = o;
        }
    }
}

// ---------------- reduce KSPLIT partials (fixed order -> deterministic) ----------------
__global__ void __launch_bounds__(256) reduceK_kernel(
    const float4* __restrict__ part, float4* __restrict__ dst)
{
    int i = blockIdx.x*256 + threadIdx.x;      // BATCH*NND*HD/4 elements
    const int S = BATCH*NND*HD/4;
    float4 o = part[i];
    #pragma unroll
    for (int zz = 1; zz < KSPLIT; zz++){
        float4 a = part[i + zz*S];
        o.x += a.x; o.y += a.y; o.z += a.z; o.w += a.w;
    }
    dst[i] = o;
}

// ---------------- z[b,t,h] = sum_n exp(2 xt.p - |p|^2 + alpha_t) * lat[b,n,h] ----------------
__global__ void __launch_bounds__(256) gatherz_kernel(
    const float* __restrict__ xt, const float* __restrict__ pos,
    const float* __restrict__ alpha, const float* __restrict__ lat,
    float* __restrict__ z)
{
    __shared__ __align__(16) float Ss[32*AS_STRIDE];   // [n-local][t-local]
    __shared__ __align__(16) ull   Ls2[32*HD];
    __shared__ float sx0[64], sx1[64], sal[64];
    int tid = threadIdx.x;
    int tx = tid & 15, ty = tid >> 4;
    int b = blockIdx.y, t0 = blockIdx.x*64;

    if (tid < 64){
        int trow = b*NTPT + t0 + tid;
        float2 x = reinterpret_cast<const float2*>(xt)[trow];
        sx0[tid] = x.x; sx1[tid] = x.y; sal[tid] = alpha[trow];
    }
    ull acc[2][8];
    #pragma unroll
    for (int r = 0; r < 2; r++)
        #pragma unroll
        for (int j = 0; j < 8; j++) acc[r][j] = 0ULL;

    for (int nn = 0; nn < NND; nn += 32){
        __syncthreads();
        #pragma unroll
        for (int i = 0; i < 16; i++){
            int e = tid + i*256;
            float w = lat[(b*NND + nn)*HD + e];
            Ls2[e] = pk2(w, w);
        }
        #pragma unroll
        for (int i = 0; i < 8; i++){
            int e = tid + i*256;
            int nl = e >> 6, tl = e & 63;
            float2 p = reinterpret_cast<const float2*>(pos)[nn + nl];
            Ss[nl*AS_STRIDE + tl] = __expf(2.f*(sx0[tl]*p.x + sx1[tl]*p.y)
                                           - (p.x*p.x + p.y*p.y) + sal[tl]);
        }
        __syncthreads();
        mma_rows4(acc, Ss, Ls2, ty, tx);
    }
    #pragma unroll
    for (int r = 0; r < 4; r++){
        int rp = r >> 1, s = r & 1;
        int row = b*NTPT + t0 + ty*4 + r;
        #pragma unroll
        for (int j = 0; j < 4; j++){
            float2 p0 = upk(acc[rp][2*j]);
            float2 p1 = upk(acc[rp][2*j+1]);
            float2 o; o.x = (s ? p0.y : p0.x); o.y = (s ? p1.y : p1.x);
            *reinterpret_cast<float2*>(&z[row*HD + 2*tx + 32*j]) = o;
        }
    }
}

// ---------------- CSR build (deterministic after per-bucket sort) ----------------
__global__ void csr_zero_kernel(int* cnt){ cnt[blockIdx.x*256 + threadIdx.x] = 0; }
__global__ void csr_count_kernel(const int* __restrict__ recv, int* cnt){
    int e = blockIdx.x*256 + threadIdx.x;
    atomicAdd(&cnt[recv[e]], 1);
}
__global__ void csr_scan_kernel(const int* __restrict__ cnt, int* off, int* cur){
    __shared__ int s[NND];
    int t = threadIdx.x;
    s[t] = cnt[t]; __syncthreads();
    for (int d = 1; d < NND; d <<= 1){
        int v = (t >= d) ? s[t-d] : 0;
        __syncthreads();
        s[t] += v;
        __syncthreads();
    }
    int excl = s[t] - cnt[t];
    off[t] = excl; cur[t] = excl;
    if (t == NND-1) off[NND] = s[NND-1];
}
__global__ void csr_fill_kernel(const int* __restrict__ recv, int* cur, int* csr){
    int e = blockIdx.x*256 + threadIdx.x;
    int slot = atomicAdd(&cur[recv[e]], 1);
    csr[slot] = e;
}
__global__ void csr_sort_kernel(const int* __restrict__ off, int* csr){
    int n = blockIdx.x*256 + threadIdx.x;
    if (n >= NND) return;
    int s0 = off[n], s1 = off[n+1];
    for (int i = s0+1; i < s1; i++){
        int v = csr[i], j = i-1;
        while (j >= s0 && csr[j] > v){ csr[j+1] = csr[j]; j--; }
        csr[j+1] = v;
    }
}

// ---------------- per (b,node) in-edge accumulation with edge LayerNorm ----------------
__global__ void __launch_bounds__(256) inbox_kernel(
    const float* __restrict__ NR, const float* __restrict__ NS,
    const float* __restrict__ lg, const float* __restrict__ lb,
    const int* __restrict__ senders, const int* __restrict__ off,
    const int* __restrict__ csr, float* __restrict__ inbox)
{
    int w = (blockIdx.x*256 + threadIdx.x) >> 5;
    int lane = threadIdx.x & 31;
    int b = w / NND, n = w - b*NND;
    int c0 = lane*4;
    float4 nr = *reinterpret_cast<const float4*>(&NR[(b*NND+n)*HD + c0]);
    float4 gl = *reinterpret_cast<const float4*>(&lg[c0]);
    float4 bl = *reinterpret_cast<const float4*>(&lb[c0]);
    float a0=0.f, a1=0.f, a2=0.f, a3=0.f;
    int s0 = off[n], s1 = off[n+1];
    for (int i = s0; i < s1; i++){
        int e = csr[i];
        int s = senders[e];
        float4 ns = *reinterpret_cast<const float4*>(&NS[(b*NND+s)*HD + c0]);
        float v0 = nr.x+ns.x, v1 = nr.y+ns.y, v2 = nr.z+ns.z, v3 = nr.w+ns.w;
        float sm = v0+v1+v2+v3;
        float sq = v0*v0+v1*v1+v2*v2+v3*v3;
        #pragma unroll
        for (int d = 1; d < 32; d <<= 1){
            sm += __shfl_xor_sync(0xffffffffu, sm, d);
            sq += __shfl_xor_sync(0xffffffffu, sq, d);
        }
        float mu = sm*(1.f/HD);
        float rs = rsqrtf(sq*(1.f/HD) - mu*mu + LNEPS);
        a0 += (v0-mu)*rs*gl.x + bl.x;
        a1 += (v1-mu)*rs*gl.y + bl.y;
        a2 += (v2-mu)*rs*gl.z + bl.z;
        a3 += (v3-mu)*rs*gl.w + bl.w;
    }
    float4 o; o.x=a0; o.y=a1; o.z=a2; o.w=a3;
    *reinterpret_cast<float4*>(&inbox[(b*NND+n)*HD + c0]) = o;
}

// ---------------- final decoder layer [.,128]@[128,3] (warp per row) ----------------
__global__ void __launch_bounds__(256) dec_final_kernel(
    const float* __restrict__ Hh, const float* __restrict__ W2,
    const float* __restrict__ b2, float* __restrict__ out)
{
    int w = (blockIdx.x*256 + threadIdx.x) >> 5;
    int lane = threadIdx.x & 31;
    float4 h = *reinterpret_cast<const float4*>(&Hh[w*HD + lane*4]);
    int k0 = lane*4;
    float a[3];
    #pragma unroll
    for (int j = 0; j < 3; j++)
        a[j] = h.x*W2[k0*3+j] + h.y*W2[(k0+1)*3+j] + h.z*W2[(k0+2)*3+j] + h.w*W2[(k0+3)*3+j];
    #pragma unroll
    for (int d = 1; d < 32; d <<= 1){
        #pragma unroll
        for (int j = 0; j < 3; j++) a[j] += __shfl_xor_sync(0xffffffffu, a[j], d);
    }
    if (lane == 0){
        #pragma unroll
        for (int j = 0; j < 3; j++) out[w*3 + j] = a[j] + b2[j];
    }
}

// ---------------- host ----------------
extern "C" void kernel_launch(void* const* d_in, const int* in_sizes, int n_in,
                              void* d_out, int out_size)
{
    const float* xc   = (const float*)d_in[0];
    const float* yc   = (const float*)d_in[1];
    const float* xt   = (const float*)d_in[2];
    const float* pos  = (const float*)d_in[3];
    const float* enc_W0 = (const float*)d_in[4];  const float* enc_b0 = (const float*)d_in[5];
    const float* enc_W1 = (const float*)d_in[6];  const float* enc_b1 = (const float*)d_in[7];
    const float* enc_W2 = (const float*)d_in[8];  const float* enc_b2 = (const float*)d_in[9];
    const float* qenc_W0 = (const float*)d_in[10]; const float* qenc_b0 = (const float*)d_in[11];
    const float* qenc_W1 = (const float*)d_in[12]; const float* qenc_b1 = (const float*)d_in[13];
    const float* qenc_W2 = (const float*)d_in[14]; const float* qenc_b2 = (const float*)d_in[15];
    const float* dec_W0 = (const float*)d_in[16]; const float* dec_b0 = (const float*)d_in[17];
    const float* dec_W1 = (const float*)d_in[18]; const float* dec_b1 = (const float*)d_in[19];
    const float* dec_W2 = (const float*)d_in[20]; const float* dec_b2 = (const float*)d_in[21];
    const float* msg_W  = (const float*)d_in[22]; const float* msg_b  = (const float*)d_in[23];
    const float* ln1_g  = (const float*)d_in[24]; const float* ln1_b  = (const float*)d_in[25];
    const float* node_W = (const float*)d_in[26]; const float* node_b = (const float*)d_in[27];
    const float* ln2_g  = (const float*)d_in[28]; const float* ln2_b  = (const float*)d_in[29];
    const int* senders   = (const int*)d_in[30];
    const int* receivers = (const int*)d_in[31];
    float* out = (float*)d_out;

    void* p;
    cudaGetSymbolAddress(&p, g_tmpA); float* tmpA = (float*)p;
    cudaGetSymbolAddress(&p, g_tmpB); float* tmpB = (float*)p;
    cudaGetSymbolAddress(&p, g_emb);  float* emb  = (float*)p;
    cudaGetSymbolAddress(&p, g_q);    float* q    = (float*)p;
    cudaGetSymbolAddress(&p, g_z);    float* z    = (float*)p;
    cudaGetSymbolAddress(&p, g_latA); float* latA = (float*)p;
    cudaGetSymbolAddress(&p, g_latB); float* latB = (float*)p;
    cudaGetSymbolAddress(&p, g_NR);   float* NR   = (float*)p;
    cudaGetSymbolAddress(&p, g_NS);   float* NS   = (float*)p;
    cudaGetSymbolAddress(&p, g_inb);  float* inb  = (float*)p;
    cudaGetSymbolAddress(&p, g_alC);  float* alC  = (float*)p;
    cudaGetSymbolAddress(&p, g_alT);  float* alT  = (float*)p;
    cudaGetSymbolAddress(&p, g_cnt);  int* cnt = (int*)p;
    cudaGetSymbolAddress(&p, g_cur);  int* cur = (int*)p;
    cudaGetSymbolAddress(&p, g_off);  int* off = (int*)p;
    cudaGetSymbolAddress(&p, g_csr);  int* csr = (int*)p;

    const int rows_c = BATCH*NCPT;      // 32768
    const int rows_t = BATCH*NTPT;      // 32768
    const int rows_n = BATCH*NND;       // 8192

    // --- encoder MLP on context points (launches 0-2) ---
    mlp_l1_kernel<<<rows_c, HD>>>(xc, 2, yc, 3, enc_W0, enc_b0, tmpA);
    gemm128_kernel<2><<<rows_c/64, 256>>>(tmpA, tmpA, enc_W1, enc_b1, 0, 0, tmpB, 128);
    gemm128_kernel<1><<<rows_c/64, 256>>>(tmpB, tmpB, enc_W2, enc_b2, 0, 0, emb, 128);

    // --- softmax normalizers (3), csr_zero (4), scatter (5, ncu target) ---
    alpha2_kernel<<<(rows_c+rows_t)/8, 256>>>(xc, xt, pos, alC, alT);
    csr_zero_kernel<<<NND/256, 256>>>(cnt);
    scatter_kernel<<<dim3(NND/64, BATCH, KSPLIT), 256>>>(xc, pos, alC, emb, tmpA);
    reduceK_kernel<<<rows_n*HD/4/256, 256>>>((const float4*)tmpA, (float4*)latA);

    // --- rest of CSR build (deterministic) ---
    csr_count_kernel<<<NE/256, 256>>>(receivers, cnt);
    csr_scan_kernel<<<1, NND>>>(cnt, off, cur);
    csr_fill_kernel<<<NE/256, 256>>>(receivers, cur, csr);
    csr_sort_kernel<<<NND/256, 256>>>(off, csr);

    // --- 4 shared-weight graph blocks ---
    float* curL = latA; float* othL = latB;
    for (int step = 0; step < 4; step++){
        gemm_msg_kernel<<<rows_n/64, 256>>>(curL, msg_W, msg_W + 128*HD, msg_b, NR, NS);
        inbox_kernel<<<rows_n/8, 256>>>(NR, NS, ln1_g, ln1_b, senders, off, csr, inb);
        gemm128_kernel<3><<<rows_n/64, 256>>>(curL, inb, node_W, node_b, ln2_g, ln2_b, othL, 256);
        float* t = curL; curL = othL; othL = t;
    }

    // --- query encoder ---
    mlp_l1_kernel<<<rows_t, HD>>>(xt, 2, xt, 0, qenc_W0, qenc_b0, tmpA);
    gemm128_kernel<2><<<rows_t/64, 256>>>(tmpA, tmpA, qenc_W1, qenc_b1, 0, 0, tmpB, 128);
    gemm128_kernel<1><<<rows_t/64, 256>>>(tmpB, tmpB, qenc_W2, qenc_b2, 0, 0, q, 128);

    // --- readout z ---
    gatherz_kernel<<<dim3(NTPT/64, BATCH), 256>>>(xt, pos, alT, curL, z);

    // --- decoder ---
    gemm128_kernel<2><<<rows_t/64, 256>>>(z, q, dec_W0, dec_b0, 0, 0, tmpA, 256);
    gemm128_kernel<2><<<rows_t/64, 256>>>(tmpA, tmpA, dec_W1, dec_b1, 0, 0, tmpB, 128);
    dec_final_kernel<<<rows_t/8, 256>>>(tmpB, dec_W2, dec_b2, out);
}

// round 12
// speedup vs baseline: 1.1601x; 1.1601x over previous
#include <cuda_runtime.h>
#include <cuda_bf16.h>

#define BATCH 8
#define NCPT 4096
#define NTPT 4096
#define NND  1024
#define NE   16384
#define HD   128
#define LNEPS 1e-5f
#define KSPLIT 4

typedef unsigned long long ull;

// ---------------- scratch (device globals; no allocation) ----------------
__device__ __align__(16) float g_tmpA[BATCH*NCPT*HD];   // reused as scatter partials [4][8192][128]
__device__ __align__(16) float g_tmpB[BATCH*NCPT*HD];
__device__ __align__(16) float g_emb [BATCH*NCPT*HD];
__device__ __align__(16) float g_q   [BATCH*NTPT*HD];
__device__ __align__(16) float g_z   [BATCH*NTPT*HD];
__device__ __align__(16) float g_latA[BATCH*NND*HD];
__device__ __align__(16) float g_latB[BATCH*NND*HD];
__device__ __align__(16) float g_NR  [BATCH*NND*HD];
__device__ __align__(16) float g_NS  [BATCH*NND*HD];
__device__ __align__(16) float g_inb [BATCH*NND*HD];
__device__ float g_alC[BATCH*NCPT];
__device__ float g_alT[BATCH*NTPT];
__device__ int   g_cnt[NND];
__device__ int   g_cur[NND];
__device__ int   g_off[NND+1];
__device__ int   g_csr[NE];

// ---------------- f32x2 helpers ----------------
__device__ __forceinline__ ull pk2(float a, float b){
    ull u; asm("mov.b64 %0,{%1,%2};" : "=l"(u) : "f"(a), "f"(b)); return u;
}
__device__ __forceinline__ void fma2(ull &c, ull a, ull b){
    asm("fma.rn.f32x2 %0,%1,%2,%0;" : "+l"(c) : "l"(a), "l"(b));
}
__device__ __forceinline__ float2 upk(ull u){
    float2 f; asm("mov.b64 {%0,%1},%2;" : "=f"(f.x), "=f"(f.y) : "l"(u)); return f;
}

// ---------------- first MLP layer, tiny K (concat A1[d1] | A2[d2]) ----------------
__global__ void mlp_l1_kernel(const float* __restrict__ A1, int d1,
                              const float* __restrict__ A2, int d2,
                              const float* __restrict__ W0, const float* __restrict__ b0,
                              float* __restrict__ out)
{
    int row = blockIdx.x;
    int c   = threadIdx.x;
    float acc = b0[c];
    for (int k = 0; k < d1; k++) acc += A1[row*d1 + k] * W0[k*HD + c];
    for (int k = 0; k < d2; k++) acc += A2[row*d2 + k] * W0[(d1+k)*HD + c];
    out[row*HD + c] = fmaxf(acc, 0.f);
}

// ---------------- alpha for both point sets in one launch ----------------
__global__ void __launch_bounds__(256) alpha2_kernel(
    const float* __restrict__ XC, const float* __restrict__ XT,
    const float* __restrict__ pos, float* __restrict__ alC, float* __restrict__ alT)
{
    int row  = blockIdx.x*8 + (threadIdx.x >> 5);
    int lane = threadIdx.x & 31;
    const float* X; float* alpha; int r;
    if (row < BATCH*NCPT){ X = XC; alpha = alC; r = row; }
    else { X = XT; alpha = alT; r = row - BATCH*NCPT; }
    float2 x = reinterpret_cast<const float2*>(X)[r];
    float l[32];
    const float2* p2 = reinterpret_cast<const float2*>(pos);
    #pragma unroll
    for (int i = 0; i < 32; i++){
        float2 p = p2[i*32 + lane];
        l[i] = 2.f*(x.x*p.x + x.y*p.y) - (p.x*p.x + p.y*p.y);
    }
    float m = l[0];
    #pragma unroll
    for (int i = 1; i < 32; i++) m = fmaxf(m, l[i]);
    #pragma unroll
    for (int d = 1; d < 32; d <<= 1) m = fmaxf(m, __shfl_xor_sync(0xffffffffu, m, d));
    float s = 0.f;
    #pragma unroll
    for (int i = 0; i < 32; i++) s += __expf(l[i] - m);
    #pragma unroll
    for (int d = 1; d < 32; d <<= 1) s += __shfl_xor_sync(0xffffffffu, s, d);
    if (lane == 0) alpha[r] = -(m + logf(s));
}

// ---------------- generic [M,K]@[K,128] GEMM, K in {128,256} (A = A1|A2 concat) ----------------
// A tile stored PRE-PACKED as (a,a) f32x2 pairs -> inner loop has zero packing movs.
// W columns {2*tx + 32*j} -> conflict-free LDS.64.
// EPI: 1=bias, 2=bias+relu, 3=bias+LayerNorm(g,bet)
template<int EPI>
__global__ void __launch_bounds__(256) gemm128_kernel(
    const float* __restrict__ A1, const float* __restrict__ A2,
    const float* __restrict__ W,  const float* __restrict__ bias,
    const float* __restrict__ g,  const float* __restrict__ bet,
    float* __restrict__ out, int K)
{
    __shared__ __align__(16) ull   As2[32*65];
    __shared__ __align__(16) float Ws[32*128];
    int tid = threadIdx.x;
    int tx = tid & 15, ty = tid >> 4;
    int row0 = blockIdx.x * 64;

    ull acc[4][4];
    #pragma unroll
    for (int r = 0; r < 4; r++)
        #pragma unroll
        for (int j = 0; j < 4; j++) acc[r][j] = 0ULL;

    int nch = K >> 5;
    for (int cc = 0; cc < nch; cc++){
        int kg = cc << 5;
        const float* Asrc = (kg < 128) ? A1 : A2;
        int koff = (kg < 128) ? kg : kg - 128;
        __syncthreads();
        #pragma unroll
        for (int i = 0; i < 8; i++){
            int e = tid + i*256;
            int m = e >> 5, k = e & 31;
            float a = Asrc[(row0 + m)*HD + koff + k];
            As2[k*65 + m] = pk2(a, a);
        }
        #pragma unroll
        for (int i = 0; i < 16; i++){
            int e = tid + i*256;
            Ws[e] = W[kg*HD + e];
        }
        __syncthreads();
        #pragma unroll
        for (int k = 0; k < 32; k++){
            ull wv[4];
            #pragma unroll
            for (int j = 0; j < 4; j++)
                wv[j] = *reinterpret_cast<const ull*>(&Ws[k*HD + 2*tx + 32*j]);
            #pragma unroll
            for (int r = 0; r < 4; r++){
                ull ad = As2[k*65 + ty*4 + r];
                #pragma unroll
                for (int j = 0; j < 4; j++) fma2(acc[r][j], ad, wv[j]);
            }
        }
    }

    float bv[8];
    #pragma unroll
    for (int j = 0; j < 4; j++){
        bv[2*j]   = bias[2*tx + 32*j];
        bv[2*j+1] = bias[2*tx + 32*j + 1];
    }
    #pragma unroll
    for (int r = 0; r < 4; r++){
        int row = row0 + ty*4 + r;
        float v[8];
        #pragma unroll
        for (int j = 0; j < 4; j++){
            float2 p = upk(acc[r][j]);
            v[2*j] = p.x + bv[2*j]; v[2*j+1] = p.y + bv[2*j+1];
        }
        if (EPI == 2){
            #pragma unroll
            for (int u = 0; u < 8; u++) v[u] = fmaxf(v[u], 0.f);
        }
        if (EPI == 3){
            float s = 0.f, s2 = 0.f;
            #pragma unroll
            for (int u = 0; u < 8; u++){ s += v[u]; s2 += v[u]*v[u]; }
            #pragma unroll
            for (int d = 1; d < 16; d <<= 1){
                s  += __shfl_xor_sync(0xffffffffu, s,  d);
                s2 += __shfl_xor_sync(0xffffffffu, s2, d);
            }
            float mu = s * (1.f/HD);
            float rs = rsqrtf(s2 * (1.f/HD) - mu*mu + LNEPS);
            #pragma unroll
            for (int j = 0; j < 4; j++){
                int c = 2*tx + 32*j;
                v[2*j]   = (v[2*j]   - mu) * rs * g[c]   + bet[c];
                v[2*j+1] = (v[2*j+1] - mu) * rs * g[c+1] + bet[c+1];
            }
        }
        #pragma unroll
        for (int j = 0; j < 4; j++){
            float2 p; p.x = v[2*j]; p.y = v[2*j+1];
            *reinterpret_cast<float2*>(&out[row*HD + 2*tx + 32*j]) = p;
        }
    }
}

// ---------------- merged message GEMM: NR = A@WR + bR, NS = A@WS (K=128) ----------------
__global__ void __launch_bounds__(256) gemm_msg_kernel(
    const float* __restrict__ A,
    const float* __restrict__ WR, const float* __restrict__ WS,
    const float* __restrict__ bR,
    float* __restrict__ outR, float* __restrict__ outS)
{
    __shared__ __align__(16) float As[32*65];
    __shared__ __align__(16) float WsR[32*128];
    __shared__ __align__(16) float WsS[32*128];
    int tid = threadIdx.x;
    int tx = tid & 15, ty = tid >> 4;
    int row0 = blockIdx.x * 64;

    ull accR[4][4], accS[4][4];
    #pragma unroll
    for (int r = 0; r < 4; r++)
        #pragma unroll
        for (int j = 0; j < 4; j++){ accR[r][j] = 0ULL; accS[r][j] = 0ULL; }

    for (int cc = 0; cc < 4; cc++){
        int kg = cc << 5;
        __syncthreads();
        #pragma unroll
        for (int i = 0; i < 8; i++){
            int e = tid + i*256;
            int m = e >> 5, k = e & 31;
            As[k*65 + m] = A[(row0 + m)*HD + kg + k];
        }
        #pragma unroll
        for (int i = 0; i < 16; i++){
            int e = tid + i*256;
            WsR[e] = WR[kg*HD + e];
            WsS[e] = WS[kg*HD + e];
        }
        __syncthreads();
        #pragma unroll
        for (int k = 0; k < 32; k++){
            ull wvR[4], wvS[4];
            #pragma unroll
            for (int j = 0; j < 4; j++){
                wvR[j] = *reinterpret_cast<const ull*>(&WsR[k*HD + 2*tx + 32*j]);
                wvS[j] = *reinterpret_cast<const ull*>(&WsS[k*HD + 2*tx + 32*j]);
            }
            #pragma unroll
            for (int r = 0; r < 4; r++){
                float a = As[k*65 + ty*4 + r];
                ull ad = pk2(a, a);
                #pragma unroll
                for (int j = 0; j < 4; j++){
                    fma2(accR[r][j], ad, wvR[j]);
                    fma2(accS[r][j], ad, wvS[j]);
                }
            }
        }
    }

    float bv[8];
    #pragma unroll
    for (int j = 0; j < 4; j++){
        bv[2*j]   = bR[2*tx + 32*j];
        bv[2*j+1] = bR[2*tx + 32*j + 1];
    }
    #pragma unroll
    for (int r = 0; r < 4; r++){
        int row = row0 + ty*4 + r;
        #pragma unroll
        for (int j = 0; j < 4; j++){
            float2 pr = upk(accR[r][j]);
            pr.x += bv[2*j]; pr.y += bv[2*j+1];
            *reinterpret_cast<float2*>(&outR[row*HD + 2*tx + 32*j]) = pr;
            float2 ps = upk(accS[r][j]);
            *reinterpret_cast<float2*>(&outS[row*HD + 2*tx + 32*j]) = ps;
        }
    }
}

// ---------------- scatter partials: part[z][b,n,h] = sum_{c in chunk z} exp(...) * emb[b,c,h] ----------------
__global__ void __launch_bounds__(256) scatter_kernel(
    const float* __restrict__ xc, const float* __restrict__ pos,
    const float* __restrict__ alpha, const float* __restrict__ emb,
    float* __restrict__ part)
{
    __shared__ __align__(16) ull   Ss2[32*33];
    __shared__ __align__(16) float Es[32*128];
    __shared__ float spx[32], spy[32], spn[32];
    int tid = threadIdx.x;
    int tx = tid & 15, ty = tid >> 4;
    int b = blockIdx.y, n0 = blockIdx.x*32;
    int z = blockIdx.z;

    if (tid < 32){
        float2 p = reinterpret_cast<const float2*>(pos)[n0 + tid];
        spx[tid] = p.x; spy[tid] = p.y; spn[tid] = p.x*p.x + p.y*p.y;
    }
    ull acc[2][4];
    #pragma unroll
    for (int r = 0; r < 2; r++)
        #pragma unroll
        for (int j = 0; j < 4; j++) acc[r][j] = 0ULL;

    int cbeg = z * (NCPT/KSPLIT);
    int cend = cbeg + (NCPT/KSPLIT);
    for (int cc = cbeg; cc < cend; cc += 32){
        __syncthreads();
        #pragma unroll
        for (int i = 0; i < 16; i++){
            int e = tid + i*256;
            Es[e] = emb[(b*NCPT + cc)*HD + e];
        }
        #pragma unroll
        for (int i = 0; i < 4; i++){
            int e = tid + i*256;
            int c = e >> 5, nl = e & 31;
            int crow = b*NCPT + cc + c;
            float2 x = reinterpret_cast<const float2*>(xc)[crow];
            float sc = __expf(2.f*(x.x*spx[nl] + x.y*spy[nl]) - spn[nl] + alpha[crow]);
            Ss2[c*33 + nl] = pk2(sc, sc);
        }
        __syncthreads();
        #pragma unroll
        for (int k = 0; k < 32; k++){
            ull wv[4];
            #pragma unroll
            for (int j = 0; j < 4; j++)
                wv[j] = *reinterpret_cast<const ull*>(&Es[k*HD + 2*tx + 32*j]);
            #pragma unroll
            for (int r = 0; r < 2; r++){
                ull ad = Ss2[k*33 + ty*2 + r];
                #pragma unroll
                for (int j = 0; j < 4; j++) fma2(acc[r][j], ad, wv[j]);
            }
        }
    }
    int zoff = z * (BATCH*NND*HD);
    #pragma unroll
    for (int r = 0; r < 2; r++){
        int row = b*NND + n0 + ty*2 + r;
        #pragma unroll
        for (int j = 0; j < 4; j++){
            float2 p = upk(acc[r][j]);
            *reinterpret_cast<float2*>(&part[zoff + row*HD + 2*tx + 32*j]) = p;
        }
    }
}

// ---------------- reduce KSPLIT partials (fixed order -> deterministic) ----------------
__global__ void __launch_bounds__(256) reduceK_kernel(
    const float4* __restrict__ part, float4* __restrict__ dst)
{
    int i = blockIdx.x*256 + threadIdx.x;
    const int S = BATCH*NND*HD/4;
    float4 o = part[i];
    #pragma unroll
    for (int zz = 1; zz < KSPLIT; zz++){
        float4 a = part[i + zz*S];
        o.x += a.x; o.y += a.y; o.z += a.z; o.w += a.w;
    }
    dst[i] = o;
}

// ---------------- z[b,t,h] = sum_n exp(2 xt.p - |p|^2 + alpha_t) * lat[b,n,h] ----------------
__global__ void __launch_bounds__(256) gatherz_kernel(
    const float* __restrict__ xt, const float* __restrict__ pos,
    const float* __restrict__ alpha, const float* __restrict__ lat,
    float* __restrict__ z)
{
    __shared__ __align__(16) ull   Ss2[32*65];
    __shared__ __align__(16) float Ls[32*128];
    __shared__ float sx0[64], sx1[64], sal[64];
    int tid = threadIdx.x;
    int tx = tid & 15, ty = tid >> 4;
    int b = blockIdx.y, t0 = blockIdx.x*64;

    if (tid < 64){
        int trow = b*NTPT + t0 + tid;
        float2 x = reinterpret_cast<const float2*>(xt)[trow];
        sx0[tid] = x.x; sx1[tid] = x.y; sal[tid] = alpha[trow];
    }
    ull acc[4][4];
    #pragma unroll
    for (int r = 0; r < 4; r++)
        #pragma unroll
        for (int j = 0; j < 4; j++) acc[r][j] = 0ULL;

    for (int nn = 0; nn < NND; nn += 32){
        __syncthreads();
        #pragma unroll
        for (int i = 0; i < 16; i++){
            int e = tid + i*256;
            Ls[e] = lat[(b*NND + nn)*HD + e];
        }
        #pragma unroll
        for (int i = 0; i < 8; i++){
            int e = tid + i*256;
            int nl = e >> 6, tl = e & 63;
            float2 p = reinterpret_cast<const float2*>(pos)[nn + nl];
            float sc = __expf(2.f*(sx0[tl]*p.x + sx1[tl]*p.y)
                              - (p.x*p.x + p.y*p.y) + sal[tl]);
            Ss2[nl*65 + tl] = pk2(sc, sc);
        }
        __syncthreads();
        #pragma unroll
        for (int k = 0; k < 32; k++){
            ull wv[4];
            #pragma unroll
            for (int j = 0; j < 4; j++)
                wv[j] = *reinterpret_cast<const ull*>(&Ls[k*HD + 2*tx + 32*j]);
            #pragma unroll
            for (int r = 0; r < 4; r++){
                ull ad = Ss2[k*65 + ty*4 + r];
                #pragma unroll
                for (int j = 0; j < 4; j++) fma2(acc[r][j], ad, wv[j]);
            }
        }
    }
    #pragma unroll
    for (int r = 0; r < 4; r++){
        int row = b*NTPT + t0 + ty*4 + r;
        #pragma unroll
        for (int j = 0; j < 4; j++){
            float2 p = upk(acc[r][j]);
            *reinterpret_cast<float2*>(&z[row*HD + 2*tx + 32*j]) = p;
        }
    }
}

// ---------------- CSR build (deterministic after per-bucket sort) ----------------
__global__ void csr_zero_kernel(int* cnt){ cnt[blockIdx.x*256 + threadIdx.x] = 0; }
__global__ void csr_count_kernel(const int* __restrict__ recv, int* cnt){
    int e = blockIdx.x*256 + threadIdx.x;
    atomicAdd(&cnt[recv[e]], 1);
}
__global__ void csr_scan_kernel(const int* __restrict__ cnt, int* off, int* cur){
    __shared__ int s[NND];
    int t = threadIdx.x;
    s[t] = cnt[t]; __syncthreads();
    for (int d = 1; d < NND; d <<= 1){
        int v = (t >= d) ? s[t-d] : 0;
        __syncthreads();
        s[t] += v;
        __syncthreads();
    }
    int excl = s[t] - cnt[t];
    off[t] = excl; cur[t] = excl;
    if (t == NND-1) off[NND] = s[NND-1];
}
__global__ void csr_fill_kernel(const int* __restrict__ recv, int* cur, int* csr){
    int e = blockIdx.x*256 + threadIdx.x;
    int slot = atomicAdd(&cur[recv[e]], 1);
    csr[slot] = e;
}
__global__ void csr_sort_kernel(const int* __restrict__ off, int* csr){
    int n = blockIdx.x*256 + threadIdx.x;
    if (n >= NND) return;
    int s0 = off[n], s1 = off[n+1];
    for (int i = s0+1; i < s1; i++){
        int v = csr[i], j = i-1;
        while (j >= s0 && csr[j] > v){ csr[j+1] = csr[j]; j--; }
        csr[j+1] = v;
    }
}

// ---------------- per (b,node) in-edge accumulation with edge LayerNorm ----------------
__global__ void __launch_bounds__(256) inbox_kernel(
    const float* __restrict__ NR, const float* __restrict__ NS,
    const float* __restrict__ lg, const float* __restrict__ lb,
    const int* __restrict__ senders, const int* __restrict__ off,
    const int* __restrict__ csr, float* __restrict__ inbox)
{
    int w = (blockIdx.x*256 + threadIdx.x) >> 5;
    int lane = threadIdx.x & 31;
    int b = w / NND, n = w - b*NND;
    int c0 = lane*4;
    float4 nr = *reinterpret_cast<const float4*>(&NR[(b*NND+n)*HD + c0]);
    float4 gl = *reinterpret_cast<const float4*>(&lg[c0]);
    float4 bl = *reinterpret_cast<const float4*>(&lb[c0]);
    float a0=0.f, a1=0.f, a2=0.f, a3=0.f;
    int s0 = off[n], s1 = off[n+1];
    for (int i = s0; i < s1; i++){
        int e = csr[i];
        int s = senders[e];
        float4 ns = *reinterpret_cast<const float4*>(&NS[(b*NND+s)*HD + c0]);
        float v0 = nr.x+ns.x, v1 = nr.y+ns.y, v2 = nr.z+ns.z, v3 = nr.w+ns.w;
        float sm = v0+v1+v2+v3;
        float sq = v0*v0+v1*v1+v2*v2+v3*v3;
        #pragma unroll
        for (int d = 1; d < 32; d <<= 1){
            sm += __shfl_xor_sync(0xffffffffu, sm, d);
            sq += __shfl_xor_sync(0xffffffffu, sq, d);
        }
        float mu = sm*(1.f/HD);
        float rs = rsqrtf(sq*(1.f/HD) - mu*mu + LNEPS);
        a0 += (v0-mu)*rs*gl.x + bl.x;
        a1 += (v1-mu)*rs*gl.y + bl.y;
        a2 += (v2-mu)*rs*gl.z + bl.z;
        a3 += (v3-mu)*rs*gl.w + bl.w;
    }
    float4 o; o.x=a0; o.y=a1; o.z=a2; o.w=a3;
    *reinterpret_cast<float4*>(&inbox[(b*NND+n)*HD + c0]) = o;
}

// ---------------- final decoder layer [.,128]@[128,3] (warp per row) ----------------
__global__ void __launch_bounds__(256) dec_final_kernel(
    const float* __restrict__ Hh, const float* __restrict__ W2,
    const float* __restrict__ b2, float* __restrict__ out)
{
    int w = (blockIdx.x*256 + threadIdx.x) >> 5;
    int lane = threadIdx.x & 31;
    float4 h = *reinterpret_cast<const float4*>(&Hh[w*HD + lane*4]);
    int k0 = lane*4;
    float a[3];
    #pragma unroll
    for (int j = 0; j < 3; j++)
        a[j] = h.x*W2[k0*3+j] + h.y*W2[(k0+1)*3+j] + h.z*W2[(k0+2)*3+j] + h.w*W2[(k0+3)*3+j];
    #pragma unroll
    for (int d = 1; d < 32; d <<= 1){
        #pragma unroll
        for (int j = 0; j < 3; j++) a[j] += __shfl_xor_sync(0xffffffffu, a[j], d);
    }
    if (lane == 0){
        #pragma unroll
        for (int j = 0; j < 3; j++) out[w*3 + j] = a[j] + b2[j];
    }
}

// ---------------- host ----------------
extern "C" void kernel_launch(void* const* d_in, const int* in_sizes, int n_in,
                              void* d_out, int out_size)
{
    const float* xc   = (const float*)d_in[0];
    const float* yc   = (const float*)d_in[1];
    const float* xt   = (const float*)d_in[2];
    const float* pos  = (const float*)d_in[3];
    const float* enc_W0 = (const float*)d_in[4];  const float* enc_b0 = (const float*)d_in[5];
    const float* enc_W1 = (const float*)d_in[6];  const float* enc_b1 = (const float*)d_in[7];
    const float* enc_W2 = (const float*)d_in[8];  const float* enc_b2 = (const float*)d_in[9];
    const float* qenc_W0 = (const float*)d_in[10]; const float* qenc_b0 = (const float*)d_in[11];
    const float* qenc_W1 = (const float*)d_in[12]; const float* qenc_b1 = (const float*)d_in[13];
    const float* qenc_W2 = (const float*)d_in[14]; const float* qenc_b2 = (const float*)d_in[15];
    const float* dec_W0 = (const float*)d_in[16]; const float* dec_b0 = (const float*)d_in[17];
    const float* dec_W1 = (const float*)d_in[18]; const float* dec_b1 = (const float*)d_in[19];
    const float* dec_W2 = (const float*)d_in[20]; const float* dec_b2 = (const float*)d_in[21];
    const float* msg_W  = (const float*)d_in[22]; const float* msg_b  = (const float*)d_in[23];
    const float* ln1_g  = (const float*)d_in[24]; const float* ln1_b  = (const float*)d_in[25];
    const float* node_W = (const float*)d_in[26]; const float* node_b = (const float*)d_in[27];
    const float* ln2_g  = (const float*)d_in[28]; const float* ln2_b  = (const float*)d_in[29];
    const int* senders   = (const int*)d_in[30];
    const int* receivers = (const int*)d_in[31];
    float* out = (float*)d_out;

    void* p;
    cudaGetSymbolAddress(&p, g_tmpA); float* tmpA = (float*)p;
    cudaGetSymbolAddress(&p, g_tmpB); float* tmpB = (float*)p;
    cudaGetSymbolAddress(&p, g_emb);  float* emb  = (float*)p;
    cudaGetSymbolAddress(&p, g_q);    float* q    = (float*)p;
    cudaGetSymbolAddress(&p, g_z);    float* z    = (float*)p;
    cudaGetSymbolAddress(&p, g_latA); float* latA = (float*)p;
    cudaGetSymbolAddress(&p, g_latB); float* latB = (float*)p;
    cudaGetSymbolAddress(&p, g_NR);   float* NR   = (float*)p;
    cudaGetSymbolAddress(&p, g_NS);   float* NS   = (float*)p;
    cudaGetSymbolAddress(&p, g_inb);  float* inb  = (float*)p;
    cudaGetSymbolAddress(&p, g_alC);  float* alC  = (float*)p;
    cudaGetSymbolAddress(&p, g_alT);  float* alT  = (float*)p;
    cudaGetSymbolAddress(&p, g_cnt);  int* cnt = (int*)p;
    cudaGetSymbolAddress(&p, g_cur);  int* cur = (int*)p;
    cudaGetSymbolAddress(&p, g_off);  int* off = (int*)p;
    cudaGetSymbolAddress(&p, g_csr);  int* csr = (int*)p;

    const int rows_c = BATCH*NCPT;      // 32768
    const int rows_t = BATCH*NTPT;      // 32768
    const int rows_n = BATCH*NND;       // 8192

    // --- encoder MLP on context points (launches 0-2) ---
    mlp_l1_kernel<<<rows_c, HD>>>(xc, 2, yc, 3, enc_W0, enc_b0, tmpA);
    gemm128_kernel<2><<<rows_c/64, 256>>>(tmpA, tmpA, enc_W1, enc_b1, 0, 0, tmpB, 128);
    gemm128_kernel<1><<<rows_c/64, 256>>>(tmpB, tmpB, enc_W2, enc_b2, 0, 0, emb, 128);

    // --- softmax normalizers (3), csr_zero (4), scatter (5, ncu target) ---
    alpha2_kernel<<<(rows_c+rows_t)/8, 256>>>(xc, xt, pos, alC, alT);
    csr_zero_kernel<<<NND/256, 256>>>(cnt);
    scatter_kernel<<<dim3(NND/32, BATCH, KSPLIT), 256>>>(xc, pos, alC, emb, tmpA);
    reduceK_kernel<<<rows_n*HD/4/256, 256>>>((const float4*)tmpA, (float4*)latA);

    // --- rest of CSR build (deterministic) ---
    csr_count_kernel<<<NE/256, 256>>>(receivers, cnt);
    csr_scan_kernel<<<1, NND>>>(cnt, off, cur);
    csr_fill_kernel<<<NE/256, 256>>>(receivers, cur, csr);
    csr_sort_kernel<<<NND/256, 256>>>(off, csr);

    // --- 4 shared-weight graph blocks ---
    float* curL = latA; float* othL = latB;
    for (int step = 0; step < 4; step++){
        gemm_msg_kernel<<<rows_n/64, 256>>>(curL, msg_W, msg_W + 128*HD, msg_b, NR, NS);
        inbox_kernel<<<rows_n/8, 256>>>(NR, NS, ln1_g, ln1_b, senders, off, csr, inb);
        gemm128_kernel<3><<<rows_n/64, 256>>>(curL, inb, node_W, node_b, ln2_g, ln2_b, othL, 256);
        float* t = curL; curL = othL; othL = t;
    }

    // --- query encoder ---
    mlp_l1_kernel<<<rows_t, HD>>>(xt, 2, xt, 0, qenc_W0, qenc_b0, tmpA);
    gemm128_kernel<2><<<rows_t/64, 256>>>(tmpA, tmpA, qenc_W1, qenc_b1, 0, 0, tmpB, 128);
    gemm128_kernel<1><<<rows_t/64, 256>>>(tmpB, tmpB, qenc_W2, qenc_b2, 0, 0, q, 128);

    // --- readout z ---
    gatherz_kernel<<<dim3(NTPT/64, BATCH), 256>>>(xt, pos, alT, curL, z);

    // --- decoder ---
    gemm128_kernel<2><<<rows_t/64, 256>>>(z, q, dec_W0, dec_b0, 0, 0, tmpA, 256);
    gemm128_kernel<2><<<rows_t/64, 256>>>(tmpA, tmpA, dec_W1, dec_b1, 0, 0, tmpB, 128);
    dec_final_kernel<<<rows_t/8, 256>>>(tmpB, dec_W2, dec_b2, out);
}

// round 14
// speedup vs baseline: 1.1899x; 1.0257x over previous
#include <cuda_runtime.h>
#include <cuda_bf16.h>

#define BATCH 8
#define NCPT 4096
#define NTPT 4096
#define NND  1024
#define NE   16384
#define HD   128
#define LNEPS 1e-5f
#define KSPLIT 4

typedef unsigned long long ull;

// ---------------- scratch (device globals; no allocation) ----------------
__device__ __align__(16) float g_tmpA[BATCH*NCPT*HD];   // reused as scatter partials [4][8192][128]
__device__ __align__(16) float g_tmpB[BATCH*NCPT*HD];
__device__ __align__(16) float g_emb [BATCH*NCPT*HD];
__device__ __align__(16) float g_q   [BATCH*NTPT*HD];
__device__ __align__(16) float g_z   [BATCH*NTPT*HD];
__device__ __align__(16) float g_latA[BATCH*NND*HD];
__device__ __align__(16) float g_latB[BATCH*NND*HD];
__device__ __align__(16) float g_NR  [BATCH*NND*HD];
__device__ __align__(16) float g_NS  [BATCH*NND*HD];
__device__ __align__(16) float g_inb [BATCH*NND*HD];
__device__ float g_alC[BATCH*NCPT];
__device__ float g_alT[BATCH*NTPT];
__device__ int   g_cnt[NND];
__device__ int   g_cur[NND];
__device__ int   g_off[NND+1];
__device__ int   g_csr[NE];

// ---------------- f32x2 helpers ----------------
__device__ __forceinline__ ull pk2(float a, float b){
    ull u; asm("mov.b64 %0,{%1,%2};" : "=l"(u) : "f"(a), "f"(b)); return u;
}
__device__ __forceinline__ void fma2(ull &c, ull a, ull b){
    asm("fma.rn.f32x2 %0,%1,%2,%0;" : "+l"(c) : "l"(a), "l"(b));
}
__device__ __forceinline__ float2 upk(ull u){
    float2 f; asm("mov.b64 {%0,%1},%2;" : "=f"(f.x), "=f"(f.y) : "l"(u)); return f;
}

// ---------------- first MLP layer, tiny K (concat A1[d1] | A2[d2]) ----------------
__global__ void mlp_l1_kernel(const float* __restrict__ A1, int d1,
                              const float* __restrict__ A2, int d2,
                              const float* __restrict__ W0, const float* __restrict__ b0,
                              float* __restrict__ out)
{
    int row = blockIdx.x;
    int c   = threadIdx.x;
    float acc = b0[c];
    for (int k = 0; k < d1; k++) acc += A1[row*d1 + k] * W0[k*HD + c];
    for (int k = 0; k < d2; k++) acc += A2[row*d2 + k] * W0[(d1+k)*HD + c];
    out[row*HD + c] = fmaxf(acc, 0.f);
}

// ---------------- alpha for both point sets in one launch ----------------
__global__ void __launch_bounds__(256) alpha2_kernel(
    const float* __restrict__ XC, const float* __restrict__ XT,
    const float* __restrict__ pos, float* __restrict__ alC, float* __restrict__ alT)
{
    int row  = blockIdx.x*8 + (threadIdx.x >> 5);
    int lane = threadIdx.x & 31;
    const float* X; float* alpha; int r;
    if (row < BATCH*NCPT){ X = XC; alpha = alC; r = row; }
    else { X = XT; alpha = alT; r = row - BATCH*NCPT; }
    float2 x = reinterpret_cast<const float2*>(X)[r];
    float l[32];
    const float2* p2 = reinterpret_cast<const float2*>(pos);
    #pragma unroll
    for (int i = 0; i < 32; i++){
        float2 p = p2[i*32 + lane];
        l[i] = 2.f*(x.x*p.x + x.y*p.y) - (p.x*p.x + p.y*p.y);
    }
    float m = l[0];
    #pragma unroll
    for (int i = 1; i < 32; i++) m = fmaxf(m, l[i]);
    #pragma unroll
    for (int d = 1; d < 32; d <<= 1) m = fmaxf(m, __shfl_xor_sync(0xffffffffu, m, d));
    float s = 0.f;
    #pragma unroll
    for (int i = 0; i < 32; i++) s += __expf(l[i] - m);
    #pragma unroll
    for (int d = 1; d < 32; d <<= 1) s += __shfl_xor_sync(0xffffffffu, s, d);
    if (lane == 0) alpha[r] = -(m + logf(s));
}

// ---------------- generic [M,K]@[K,128] GEMM, 64-row tile (R10-verified) ----------------
// EPI: 1=bias, 2=bias+relu, 3=bias+LayerNorm(g,bet)
template<int EPI>
__global__ void __launch_bounds__(256) gemm128_kernel(
    const float* __restrict__ A1, const float* __restrict__ A2,
    const float* __restrict__ W,  const float* __restrict__ bias,
    const float* __restrict__ g,  const float* __restrict__ bet,
    float* __restrict__ out, int K)
{
    __shared__ __align__(16) float As[32*65];
    __shared__ __align__(16) float Ws[32*128];
    int tid = threadIdx.x;
    int tx = tid & 15, ty = tid >> 4;
    int row0 = blockIdx.x * 64;

    ull acc[4][4];
    #pragma unroll
    for (int r = 0; r < 4; r++)
        #pragma unroll
        for (int j = 0; j < 4; j++) acc[r][j] = 0ULL;

    int nch = K >> 5;
    for (int cc = 0; cc < nch; cc++){
        int kg = cc << 5;
        const float* Asrc = (kg < 128) ? A1 : A2;
        int koff = (kg < 128) ? kg : kg - 128;
        __syncthreads();
        #pragma unroll
        for (int i = 0; i < 8; i++){
            int e = tid + i*256;
            int m = e >> 5, k = e & 31;
            As[k*65 + m] = Asrc[(row0 + m)*HD + koff + k];
        }
        #pragma unroll
        for (int i = 0; i < 16; i++){
            int e = tid + i*256;
            Ws[e] = W[kg*HD + e];
        }
        __syncthreads();
        #pragma unroll
        for (int k = 0; k < 32; k++){
            ull wv[4];
            #pragma unroll
            for (int j = 0; j < 4; j++)
                wv[j] = *reinterpret_cast<const ull*>(&Ws[k*HD + 2*tx + 32*j]);
            #pragma unroll
            for (int r = 0; r < 4; r++){
                float a = As[k*65 + ty*4 + r];
                ull ad = pk2(a, a);
                #pragma unroll
                for (int j = 0; j < 4; j++) fma2(acc[r][j], ad, wv[j]);
            }
        }
    }

    float bv[8];
    #pragma unroll
    for (int j = 0; j < 4; j++){
        bv[2*j]   = bias[2*tx + 32*j];
        bv[2*j+1] = bias[2*tx + 32*j + 1];
    }
    #pragma unroll
    for (int r = 0; r < 4; r++){
        int row = row0 + ty*4 + r;
        float v[8];
        #pragma unroll
        for (int j = 0; j < 4; j++){
            float2 p = upk(acc[r][j]);
            v[2*j] = p.x + bv[2*j]; v[2*j+1] = p.y + bv[2*j+1];
        }
        if (EPI == 2){
            #pragma unroll
            for (int u = 0; u < 8; u++) v[u] = fmaxf(v[u], 0.f);
        }
        if (EPI == 3){
            float s = 0.f, s2 = 0.f;
            #pragma unroll
            for (int u = 0; u < 8; u++){ s += v[u]; s2 += v[u]*v[u]; }
            #pragma unroll
            for (int d = 1; d < 16; d <<= 1){
                s  += __shfl_xor_sync(0xffffffffu, s,  d);
                s2 += __shfl_xor_sync(0xffffffffu, s2, d);
            }
            float mu = s * (1.f/HD);
            float rs = rsqrtf(s2 * (1.f/HD) - mu*mu + LNEPS);
            #pragma unroll
            for (int j = 0; j < 4; j++){
                int c = 2*tx + 32*j;
                v[2*j]   = (v[2*j]   - mu) * rs * g[c]   + bet[c];
                v[2*j+1] = (v[2*j+1] - mu) * rs * g[c+1] + bet[c+1];
            }
        }
        #pragma unroll
        for (int j = 0; j < 4; j++){
            float2 p; p.x = v[2*j]; p.y = v[2*j+1];
            *reinterpret_cast<float2*>(&out[row*HD + 2*tx + 32*j]) = p;
        }
    }
}

// ---------------- 32-row tile GEMM for small-M graph-loop launches ----------------
// Same verified inner-loop shape as scatter (acc[2][4], broadcast A reads).
template<int EPI>
__global__ void __launch_bounds__(256) gemm32_kernel(
    const float* __restrict__ A1, const float* __restrict__ A2,
    const float* __restrict__ W,  const float* __restrict__ bias,
    const float* __restrict__ g,  const float* __restrict__ bet,
    float* __restrict__ out, int K)
{
    __shared__ __align__(16) float As[32*33];
    __shared__ __align__(16) float Ws[32*128];
    int tid = threadIdx.x;
    int tx = tid & 15, ty = tid >> 4;
    int row0 = blockIdx.x * 32;

    ull acc[2][4];
    #pragma unroll
    for (int r = 0; r < 2; r++)
        #pragma unroll
        for (int j = 0; j < 4; j++) acc[r][j] = 0ULL;

    int nch = K >> 5;
    for (int cc = 0; cc < nch; cc++){
        int kg = cc << 5;
        const float* Asrc = (kg < 128) ? A1 : A2;
        int koff = (kg < 128) ? kg : kg - 128;
        __syncthreads();
        #pragma unroll
        for (int i = 0; i < 4; i++){
            int e = tid + i*256;
            int m = e >> 5, k = e & 31;
            As[k*33 + m] = Asrc[(row0 + m)*HD + koff + k];
        }
        #pragma unroll
        for (int i = 0; i < 16; i++){
            int e = tid + i*256;
            Ws[e] = W[kg*HD + e];
        }
        __syncthreads();
        #pragma unroll
        for (int k = 0; k < 32; k++){
            ull wv[4];
            #pragma unroll
            for (int j = 0; j < 4; j++)
                wv[j] = *reinterpret_cast<const ull*>(&Ws[k*HD + 2*tx + 32*j]);
            #pragma unroll
            for (int r = 0; r < 2; r++){
                float a = As[k*33 + ty*2 + r];
                ull ad = pk2(a, a);
                #pragma unroll
                for (int j = 0; j < 4; j++) fma2(acc[r][j], ad, wv[j]);
            }
        }
    }

    float bv[8];
    #pragma unroll
    for (int j = 0; j < 4; j++){
        bv[2*j]   = bias[2*tx + 32*j];
        bv[2*j+1] = bias[2*tx + 32*j + 1];
    }
    #pragma unroll
    for (int r = 0; r < 2; r++){
        int row = row0 + ty*2 + r;
        float v[8];
        #pragma unroll
        for (int j = 0; j < 4; j++){
            float2 p = upk(acc[r][j]);
            v[2*j] = p.x + bv[2*j]; v[2*j+1] = p.y + bv[2*j+1];
        }
        if (EPI == 2){
            #pragma unroll
            for (int u = 0; u < 8; u++) v[u] = fmaxf(v[u], 0.f);
        }
        if (EPI == 3){
            float s = 0.f, s2 = 0.f;
            #pragma unroll
            for (int u = 0; u < 8; u++){ s += v[u]; s2 += v[u]*v[u]; }
            #pragma unroll
            for (int d = 1; d < 16; d <<= 1){
                s  += __shfl_xor_sync(0xffffffffu, s,  d);
                s2 += __shfl_xor_sync(0xffffffffu, s2, d);
            }
            float mu = s * (1.f/HD);
            float rs = rsqrtf(s2 * (1.f/HD) - mu*mu + LNEPS);
            #pragma unroll
            for (int j = 0; j < 4; j++){
                int c = 2*tx + 32*j;
                v[2*j]   = (v[2*j]   - mu) * rs * g[c]   + bet[c];
                v[2*j+1] = (v[2*j+1] - mu) * rs * g[c+1] + bet[c+1];
            }
        }
        #pragma unroll
        for (int j = 0; j < 4; j++){
            float2 p; p.x = v[2*j]; p.y = v[2*j+1];
            *reinterpret_cast<float2*>(&out[row*HD + 2*tx + 32*j]) = p;
        }
    }
}

// ---------------- merged message GEMM, 32-row tile: NR = A@WR + bR, NS = A@WS ----------------
__global__ void __launch_bounds__(256) gemm_msg32_kernel(
    const float* __restrict__ A,
    const float* __restrict__ WR, const float* __restrict__ WS,
    const float* __restrict__ bR,
    float* __restrict__ outR, float* __restrict__ outS)
{
    __shared__ __align__(16) float As[32*33];
    __shared__ __align__(16) float WsR[32*128];
    __shared__ __align__(16) float WsS[32*128];
    int tid = threadIdx.x;
    int tx = tid & 15, ty = tid >> 4;
    int row0 = blockIdx.x * 32;

    ull accR[2][4], accS[2][4];
    #pragma unroll
    for (int r = 0; r < 2; r++)
        #pragma unroll
        for (int j = 0; j < 4; j++){ accR[r][j] = 0ULL; accS[r][j] = 0ULL; }

    for (int cc = 0; cc < 4; cc++){
        int kg = cc << 5;
        __syncthreads();
        #pragma unroll
        for (int i = 0; i < 4; i++){
            int e = tid + i*256;
            int m = e >> 5, k = e & 31;
            As[k*33 + m] = A[(row0 + m)*HD + kg + k];
        }
        #pragma unroll
        for (int i = 0; i < 16; i++){
            int e = tid + i*256;
            WsR[e] = WR[kg*HD + e];
            WsS[e] = WS[kg*HD + e];
        }
        __syncthreads();
        #pragma unroll
        for (int k = 0; k < 32; k++){
            ull wvR[4], wvS[4];
            #pragma unroll
            for (int j = 0; j < 4; j++){
                wvR[j] = *reinterpret_cast<const ull*>(&WsR[k*HD + 2*tx + 32*j]);
                wvS[j] = *reinterpret_cast<const ull*>(&WsS[k*HD + 2*tx + 32*j]);
            }
            #pragma unroll
            for (int r = 0; r < 2; r++){
                float a = As[k*33 + ty*2 + r];
                ull ad = pk2(a, a);
                #pragma unroll
                for (int j = 0; j < 4; j++){
                    fma2(accR[r][j], ad, wvR[j]);
                    fma2(accS[r][j], ad, wvS[j]);
                }
            }
        }
    }

    float bv[8];
    #pragma unroll
    for (int j = 0; j < 4; j++){
        bv[2*j]   = bR[2*tx + 32*j];
        bv[2*j+1] = bR[2*tx + 32*j + 1];
    }
    #pragma unroll
    for (int r = 0; r < 2; r++){
        int row = row0 + ty*2 + r;
        #pragma unroll
        for (int j = 0; j < 4; j++){
            float2 pr = upk(accR[r][j]);
            pr.x += bv[2*j]; pr.y += bv[2*j+1];
            *reinterpret_cast<float2*>(&outR[row*HD + 2*tx + 32*j]) = pr;
            float2 ps = upk(accS[r][j]);
            *reinterpret_cast<float2*>(&outS[row*HD + 2*tx + 32*j]) = ps;
        }
    }
}

// ---------------- scatter partials (R10-verified) ----------------
__global__ void __launch_bounds__(256) scatter_kernel(
    const float* __restrict__ xc, const float* __restrict__ pos,
    const float* __restrict__ alpha, const float* __restrict__ emb,
    float* __restrict__ part)
{
    __shared__ float Ss[32*33];
    __shared__ __align__(16) float Es[32*128];
    __shared__ float spx[32], spy[32], spn[32];
    int tid = threadIdx.x;
    int tx = tid & 15, ty = tid >> 4;
    int b = blockIdx.y, n0 = blockIdx.x*32;
    int z = blockIdx.z;

    if (tid < 32){
        float2 p = reinterpret_cast<const float2*>(pos)[n0 + tid];
        spx[tid] = p.x; spy[tid] = p.y; spn[tid] = p.x*p.x + p.y*p.y;
    }
    ull acc[2][4];
    #pragma unroll
    for (int r = 0; r < 2; r++)
        #pragma unroll
        for (int j = 0; j < 4; j++) acc[r][j] = 0ULL;

    int cbeg = z * (NCPT/KSPLIT);
    int cend = cbeg + (NCPT/KSPLIT);
    for (int cc = cbeg; cc < cend; cc += 32){
        __syncthreads();
        #pragma unroll
        for (int i = 0; i < 16; i++){
            int e = tid + i*256;
            Es[e] = emb[(b*NCPT + cc)*HD + e];
        }
        #pragma unroll
        for (int i = 0; i < 4; i++){
            int e = tid + i*256;
            int c = e >> 5, nl = e & 31;
            int crow = b*NCPT + cc + c;
            float2 x = reinterpret_cast<const float2*>(xc)[crow];
            Ss[c*33 + nl] = __expf(2.f*(x.x*spx[nl] + x.y*spy[nl]) - spn[nl] + alpha[crow]);
        }
        __syncthreads();
        #pragma unroll
        for (int k = 0; k < 32; k++){
            ull wv[4];
            #pragma unroll
            for (int j = 0; j < 4; j++)
                wv[j] = *reinterpret_cast<const ull*>(&Es[k*HD + 2*tx + 32*j]);
            #pragma unroll
            for (int r = 0; r < 2; r++){
                float a = Ss[k*33 + ty*2 + r];
                ull ad = pk2(a, a);
                #pragma unroll
                for (int j = 0; j < 4; j++) fma2(acc[r][j], ad, wv[j]);
            }
        }
    }
    int zoff = z * (BATCH*NND*HD);
    #pragma unroll
    for (int r = 0; r < 2; r++){
        int row = b*NND + n0 + ty*2 + r;
        #pragma unroll
        for (int j = 0; j < 4; j++){
            float2 p = upk(acc[r][j]);
            *reinterpret_cast<float2*>(&part[zoff + row*HD + 2*tx + 32*j]) = p;
        }
    }
}

// ---------------- reduce KSPLIT partials (fixed order -> deterministic) ----------------
__global__ void __launch_bounds__(256) reduceK_kernel(
    const float4* __restrict__ part, float4* __restrict__ dst)
{
    int i = blockIdx.x*256 + threadIdx.x;
    const int S = BATCH*NND*HD/4;
    float4 o = part[i];
    #pragma unroll
    for (int zz = 1; zz < KSPLIT; zz++){
        float4 a = part[i + zz*S];
        o.x += a.x; o.y += a.y; o.z += a.z; o.w += a.w;
    }
    dst[i] = o;
}

// ---------------- z[b,t,h] = sum_n exp(2 xt.p - |p|^2 + alpha_t) * lat[b,n,h] (R10-verified) ----------------
__global__ void __launch_bounds__(256) gatherz_kernel(
    const float* __restrict__ xt, const float* __restrict__ pos,
    const float* __restrict__ alpha, const float* __restrict__ lat,
    float* __restrict__ z)
{
    __shared__ float Ss[32*65];
    __shared__ __align__(16) float Ls[32*128];
    __shared__ float sx0[64], sx1[64], sal[64];
    int tid = threadIdx.x;
    int tx = tid & 15, ty = tid >> 4;
    int b = blockIdx.y, t0 = blockIdx.x*64;

    if (tid < 64){
        int trow = b*NTPT + t0 + tid;
        float2 x = reinterpret_cast<const float2*>(xt)[trow];
        sx0[tid] = x.x; sx1[tid] = x.y; sal[tid] = alpha[trow];
    }
    ull acc[4][4];
    #pragma unroll
    for (int r = 0; r < 4; r++)
        #pragma unroll
        for (int j = 0; j < 4; j++) acc[r][j] = 0ULL;

    for (int nn = 0; nn < NND; nn += 32){
        __syncthreads();
        #pragma unroll
        for (int i = 0; i < 16; i++){
            int e = tid + i*256;
            Ls[e] = lat[(b*NND + nn)*HD + e];
        }
        #pragma unroll
        for (int i = 0; i < 8; i++){
            int e = tid + i*256;
            int nl = e >> 6, tl = e & 63;
            float2 p = reinterpret_cast<const float2*>(pos)[nn + nl];
            Ss[nl*65 + tl] = __expf(2.f*(sx0[tl]*p.x + sx1[tl]*p.y)
                                    - (p.x*p.x + p.y*p.y) + sal[tl]);
        }
        __syncthreads();
        #pragma unroll
        for (int k = 0; k < 32; k++){
            ull wv[4];
            #pragma unroll
            for (int j = 0; j < 4; j++)
                wv[j] = *reinterpret_cast<const ull*>(&Ls[k*HD + 2*tx + 32*j]);
            #pragma unroll
            for (int r = 0; r < 4; r++){
                float a = Ss[k*65 + ty*4 + r];
                ull ad = pk2(a, a);
                #pragma unroll
                for (int j = 0; j < 4; j++) fma2(acc[r][j], ad, wv[j]);
            }
        }
    }
    #pragma unroll
    for (int r = 0; r < 4; r++){
        int row = b*NTPT + t0 + ty*4 + r;
        #pragma unroll
        for (int j = 0; j < 4; j++){
            float2 p = upk(acc[r][j]);
            *reinterpret_cast<float2*>(&z[row*HD + 2*tx + 32*j]) = p;
        }
    }
}

// ---------------- CSR build (deterministic after per-bucket sort) ----------------
__global__ void csr_zero_kernel(int* cnt){ cnt[blockIdx.x*256 + threadIdx.x] = 0; }
__global__ void csr_count_kernel(const int* __restrict__ recv, int* cnt){
    int e = blockIdx.x*256 + threadIdx.x;
    atomicAdd(&cnt[recv[e]], 1);
}
__global__ void csr_scan_kernel(const int* __restrict__ cnt, int* off, int* cur){
    __shared__ int s[NND];
    int t = threadIdx.x;
    s[t] = cnt[t]; __syncthreads();
    for (int d = 1; d < NND; d <<= 1){
        int v = (t >= d) ? s[t-d] : 0;
        __syncthreads();
        s[t] += v;
        __syncthreads();
    }
    int excl = s[t] - cnt[t];
    off[t] = excl; cur[t] = excl;
    if (t == NND-1) off[NND] = s[NND-1];
}
__global__ void csr_fill_kernel(const int* __restrict__ recv, int* cur, int* csr){
    int e = blockIdx.x*256 + threadIdx.x;
    int slot = atomicAdd(&cur[recv[e]], 1);
    csr[slot] = e;
}
__global__ void csr_sort_kernel(const int* __restrict__ off, int* csr){
    int n = blockIdx.x*256 + threadIdx.x;
    if (n >= NND) return;
    int s0 = off[n], s1 = off[n+1];
    for (int i = s0+1; i < s1; i++){
        int v = csr[i], j = i-1;
        while (j >= s0 && csr[j] > v){ csr[j+1] = csr[j]; j--; }
        csr[j+1] = v;
    }
}

// ---------------- per (b,node) in-edge accumulation with edge LayerNorm ----------------
__global__ void __launch_bounds__(256) inbox_kernel(
    const float* __restrict__ NR, const float* __restrict__ NS,
    const float* __restrict__ lg, const float* __restrict__ lb,
    const int* __restrict__ senders, const int* __restrict__ off,
    const int* __restrict__ csr, float* __restrict__ inbox)
{
    int w = (blockIdx.x*256 + threadIdx.x) >> 5;
    int lane = threadIdx.x & 31;
    int b = w / NND, n = w - b*NND;
    int c0 = lane*4;
    float4 nr = *reinterpret_cast<const float4*>(&NR[(b*NND+n)*HD + c0]);
    float4 gl = *reinterpret_cast<const float4*>(&lg[c0]);
    float4 bl = *reinterpret_cast<const float4*>(&lb[c0]);
    float a0=0.f, a1=0.f, a2=0.f, a3=0.f;
    int s0 = off[n], s1 = off[n+1];
    for (int i = s0; i < s1; i++){
        int e = csr[i];
        int s = senders[e];
        float4 ns = *reinterpret_cast<const float4*>(&NS[(b*NND+s)*HD + c0]);
        float v0 = nr.x+ns.x, v1 = nr.y+ns.y, v2 = nr.z+ns.z, v3 = nr.w+ns.w;
        float sm = v0+v1+v2+v3;
        float sq = v0*v0+v1*v1+v2*v2+v3*v3;
        #pragma unroll
        for (int d = 1; d < 32; d <<= 1){
            sm += __shfl_xor_sync(0xffffffffu, sm, d);
            sq += __shfl_xor_sync(0xffffffffu, sq, d);
        }
        float mu = sm*(1.f/HD);
        float rs = rsqrtf(sq*(1.f/HD) - mu*mu + LNEPS);
        a0 += (v0-mu)*rs*gl.x + bl.x;
        a1 += (v1-mu)*rs*gl.y + bl.y;
        a2 += (v2-mu)*rs*gl.z + bl.z;
        a3 += (v3-mu)*rs*gl.w + bl.w;
    }
    float4 o; o.x=a0; o.y=a1; o.z=a2; o.w=a3;
    *reinterpret_cast<float4*>(&inbox[(b*NND+n)*HD + c0]) = o;
}

// ---------------- final decoder layer [.,128]@[128,3] (warp per row) ----------------
__global__ void __launch_bounds__(256) dec_final_kernel(
    const float* __restrict__ Hh, const float* __restrict__ W2,
    const float* __restrict__ b2, float* __restrict__ out)
{
    int w = (blockIdx.x*256 + threadIdx.x) >> 5;
    int lane = threadIdx.x & 31;
    float4 h = *reinterpret_cast<const float4*>(&Hh[w*HD + lane*4]);
    int k0 = lane*4;
    float a[3];
    #pragma unroll
    for (int j = 0; j < 3; j++)
        a[j] = h.x*W2[k0*3+j] + h.y*W2[(k0+1)*3+j] + h.z*W2[(k0+2)*3+j] + h.w*W2[(k0+3)*3+j];
    #pragma unroll
    for (int d = 1; d < 32; d <<= 1){
        #pragma unroll
        for (int j = 0; j < 3; j++) a[j] += __shfl_xor_sync(0xffffffffu, a[j], d);
    }
    if (lane == 0){
        #pragma unroll
        for (int j = 0; j < 3; j++) out[w*3 + j] = a[j] + b2[j];
    }
}

// ---------------- host ----------------
extern "C" void kernel_launch(void* const* d_in, const int* in_sizes, int n_in,
                              void* d_out, int out_size)
{
    const float* xc   = (const float*)d_in[0];
    const float* yc   = (const float*)d_in[1];
    const float* xt   = (const float*)d_in[2];
    const float* pos  = (const float*)d_in[3];
    const float* enc_W0 = (const float*)d_in[4];  const float* enc_b0 = (const float*)d_in[5];
    const float* enc_W1 = (const float*)d_in[6];  const float* enc_b1 = (const float*)d_in[7];
    const float* enc_W2 = (const float*)d_in[8];  const float* enc_b2 = (const float*)d_in[9];
    const float* qenc_W0 = (const float*)d_in[10]; const float* qenc_b0 = (const float*)d_in[11];
    const float* qenc_W1 = (const float*)d_in[12]; const float* qenc_b1 = (const float*)d_in[13];
    const float* qenc_W2 = (const float*)d_in[14]; const float* qenc_b2 = (const float*)d_in[15];
    const float* dec_W0 = (const float*)d_in[16]; const float* dec_b0 = (const float*)d_in[17];
    const float* dec_W1 = (const float*)d_in[18]; const float* dec_b1 = (const float*)d_in[19];
    const float* dec_W2 = (const float*)d_in[20]; const float* dec_b2 = (const float*)d_in[21];
    const float* msg_W  = (const float*)d_in[22]; const float* msg_b  = (const float*)d_in[23];
    const float* ln1_g  = (const float*)d_in[24]; const float* ln1_b  = (const float*)d_in[25];
    const float* node_W = (const float*)d_in[26]; const float* node_b = (const float*)d_in[27];
    const float* ln2_g  = (const float*)d_in[28]; const float* ln2_b  = (const float*)d_in[29];
    const int* senders   = (const int*)d_in[30];
    const int* receivers = (const int*)d_in[31];
    float* out = (float*)d_out;

    void* p;
    cudaGetSymbolAddress(&p, g_tmpA); float* tmpA = (float*)p;
    cudaGetSymbolAddress(&p, g_tmpB); float* tmpB = (float*)p;
    cudaGetSymbolAddress(&p, g_emb);  float* emb  = (float*)p;
    cudaGetSymbolAddress(&p, g_q);    float* q    = (float*)p;
    cudaGetSymbolAddress(&p, g_z);    float* z    = (float*)p;
    cudaGetSymbolAddress(&p, g_latA); float* latA = (float*)p;
    cudaGetSymbolAddress(&p, g_latB); float* latB = (float*)p;
    cudaGetSymbolAddress(&p, g_NR);   float* NR   = (float*)p;
    cudaGetSymbolAddress(&p, g_NS);   float* NS   = (float*)p;
    cudaGetSymbolAddress(&p, g_inb);  float* inb  = (float*)p;
    cudaGetSymbolAddress(&p, g_alC);  float* alC  = (float*)p;
    cudaGetSymbolAddress(&p, g_alT);  float* alT  = (float*)p;
    cudaGetSymbolAddress(&p, g_cnt);  int* cnt = (int*)p;
    cudaGetSymbolAddress(&p, g_cur);  int* cur = (int*)p;
    cudaGetSymbolAddress(&p, g_off);  int* off = (int*)p;
    cudaGetSymbolAddress(&p, g_csr);  int* csr = (int*)p;

    const int rows_c = BATCH*NCPT;      // 32768
    const int rows_t = BATCH*NTPT;      // 32768
    const int rows_n = BATCH*NND;       // 8192

    // --- encoder MLP on context points (launches 0-2) ---
    mlp_l1_kernel<<<rows_c, HD>>>(xc, 2, yc, 3, enc_W0, enc_b0, tmpA);
    gemm128_kernel<2><<<rows_c/64, 256>>>(tmpA, tmpA, enc_W1, enc_b1, 0, 0, tmpB, 128);
    gemm128_kernel<1><<<rows_c/64, 256>>>(tmpB, tmpB, enc_W2, enc_b2, 0, 0, emb, 128);

    // --- softmax normalizers (3), csr_zero (4), scatter (5, ncu target) ---
    alpha2_kernel<<<(rows_c+rows_t)/8, 256>>>(xc, xt, pos, alC, alT);
    csr_zero_kernel<<<NND/256, 256>>>(cnt);
    scatter_kernel<<<dim3(NND/32, BATCH, KSPLIT), 256>>>(xc, pos, alC, emb, tmpA);
    reduceK_kernel<<<rows_n*HD/4/256, 256>>>((const float4*)tmpA, (float4*)latA);

    // --- rest of CSR build (deterministic) ---
    csr_count_kernel<<<NE/256, 256>>>(receivers, cnt);
    csr_scan_kernel<<<1, NND>>>(cnt, off, cur);
    csr_fill_kernel<<<NE/256, 256>>>(receivers, cur, csr);
    csr_sort_kernel<<<NND/256, 256>>>(off, csr);

    // --- 4 shared-weight graph blocks (32-row tiles -> 256 CTAs) ---
    float* curL = latA; float* othL = latB;
    for (int step = 0; step < 4; step++){
        gemm_msg32_kernel<<<rows_n/32, 256>>>(curL, msg_W, msg_W + 128*HD, msg_b, NR, NS);
        inbox_kernel<<<rows_n/8, 256>>>(NR, NS, ln1_g, ln1_b, senders, off, csr, inb);
        gemm32_kernel<3><<<rows_n/32, 256>>>(curL, inb, node_W, node_b, ln2_g, ln2_b, othL, 256);
        float* t = curL; curL = othL; othL = t;
    }

    // --- query encoder ---
    mlp_l1_kernel<<<rows_t, HD>>>(xt, 2, xt, 0, qenc_W0, qenc_b0, tmpA);
    gemm128_kernel<2><<<rows_t/64, 256>>>(tmpA, tmpA, qenc_W1, qenc_b1, 0, 0, tmpB, 128);
    gemm128_kernel<1><<<rows_t/64, 256>>>(tmpB, tmpB, qenc_W2, qenc_b2, 0, 0, q, 128);

    // --- readout z ---
    gatherz_kernel<<<dim3(NTPT/64, BATCH), 256>>>(xt, pos, alT, curL, z);

    // --- decoder ---
    gemm128_kernel<2><<<rows_t/64, 256>>>(z, q, dec_W0, dec_b0, 0, 0, tmpA, 256);
    gemm128_kernel<2><<<rows_t/64, 256>>>(tmpA, tmpA, dec_W1, dec_b1, 0, 0, tmpB, 128);
    dec_final_kernel<<<rows_t/8, 256>>>(tmpB, dec_W2, dec_b2, out);
}

// round 15
// speedup vs baseline: 1.4365x; 1.2072x over previous
#include <cuda_runtime.h>
#include <cuda_bf16.h>

#define BATCH 8
#define NCPT 4096
#define NTPT 4096
#define NND  1024
#define NE   16384
#define HD   128
#define LNEPS 1e-5f
#define KSPLIT 4

typedef unsigned long long ull;
typedef unsigned int uint32;

// ---------------- scratch (device globals; no allocation) ----------------
__device__ __align__(16) float g_tmpA[BATCH*NCPT*HD];   // reused as scatter partials [4][8192][128]
__device__ __align__(16) float g_tmpB[BATCH*NCPT*HD];
__device__ __align__(16) float g_emb [BATCH*NCPT*HD];
__device__ __align__(16) float g_q   [BATCH*NTPT*HD];
__device__ __align__(16) float g_z   [BATCH*NTPT*HD];
__device__ __align__(16) float g_latA[BATCH*NND*HD];
__device__ __align__(16) float g_latB[BATCH*NND*HD];
__device__ __align__(16) float g_NR  [BATCH*NND*HD];
__device__ __align__(16) float g_NS  [BATCH*NND*HD];
__device__ __align__(16) float g_inb [BATCH*NND*HD];
__device__ float g_alC[BATCH*NCPT];
__device__ float g_alT[BATCH*NTPT];
__device__ int   g_cnt[NND];
__device__ int   g_cur[NND];
__device__ int   g_off[NND+1];
__device__ int   g_csr[NE];

// ---------------- f32x2 helpers ----------------
__device__ __forceinline__ ull pk2(float a, float b){
    ull u; asm("mov.b64 %0,{%1,%2};" : "=l"(u) : "f"(a), "f"(b)); return u;
}
__device__ __forceinline__ void fma2(ull &c, ull a, ull b){
    asm("fma.rn.f32x2 %0,%1,%2,%0;" : "+l"(c) : "l"(a), "l"(b));
}
__device__ __forceinline__ float2 upk(ull u){
    float2 f; asm("mov.b64 {%0,%1},%2;" : "=f"(f.x), "=f"(f.y) : "l"(u)); return f;
}

// ---------------- bf16 mma helpers ----------------
__device__ __forceinline__ void mma16816(float c[4],
    uint32 a0, uint32 a1, uint32 a2, uint32 a3, uint32 b0, uint32 b1)
{
    asm volatile(
        "mma.sync.aligned.m16n8k16.row.col.f32.bf16.bf16.f32 "
        "{%0,%1,%2,%3}, {%4,%5,%6,%7}, {%8,%9}, {%0,%1,%2,%3};"
        : "+f"(c[0]), "+f"(c[1]), "+f"(c[2]), "+f"(c[3])
        : "r"(a0), "r"(a1), "r"(a2), "r"(a3), "r"(b0), "r"(b1));
}
__device__ __forceinline__ void split_bf16(float v, __nv_bfloat16 &hi, __nv_bfloat16 &lo){
    hi = __float2bfloat16(v);
    lo = __float2bfloat16(v - __bfloat162float(hi));
}

// ---------------- first MLP layer, tiny K (concat A1[d1] | A2[d2]) ----------------
__global__ void mlp_l1_kernel(const float* __restrict__ A1, int d1,
                              const float* __restrict__ A2, int d2,
                              const float* __restrict__ W0, const float* __restrict__ b0,
                              float* __restrict__ out)
{
    int row = blockIdx.x;
    int c   = threadIdx.x;
    float acc = b0[c];
    for (int k = 0; k < d1; k++) acc += A1[row*d1 + k] * W0[k*HD + c];
    for (int k = 0; k < d2; k++) acc += A2[row*d2 + k] * W0[(d1+k)*HD + c];
    out[row*HD + c] = fmaxf(acc, 0.f);
}

// ---------------- alpha for both point sets in one launch ----------------
__global__ void __launch_bounds__(256) alpha2_kernel(
    const float* __restrict__ XC, const float* __restrict__ XT,
    const float* __restrict__ pos, float* __restrict__ alC, float* __restrict__ alT)
{
    int row  = blockIdx.x*8 + (threadIdx.x >> 5);
    int lane = threadIdx.x & 31;
    const float* X; float* alpha; int r;
    if (row < BATCH*NCPT){ X = XC; alpha = alC; r = row; }
    else { X = XT; alpha = alT; r = row - BATCH*NCPT; }
    float2 x = reinterpret_cast<const float2*>(X)[r];
    float l[32];
    const float2* p2 = reinterpret_cast<const float2*>(pos);
    #pragma unroll
    for (int i = 0; i < 32; i++){
        float2 p = p2[i*32 + lane];
        l[i] = 2.f*(x.x*p.x + x.y*p.y) - (p.x*p.x + p.y*p.y);
    }
    float m = l[0];
    #pragma unroll
    for (int i = 1; i < 32; i++) m = fmaxf(m, l[i]);
    #pragma unroll
    for (int d = 1; d < 32; d <<= 1) m = fmaxf(m, __shfl_xor_sync(0xffffffffu, m, d));
    float s = 0.f;
    #pragma unroll
    for (int i = 0; i < 32; i++) s += __expf(l[i] - m);
    #pragma unroll
    for (int d = 1; d < 32; d <<= 1) s += __shfl_xor_sync(0xffffffffu, s, d);
    if (lane == 0) alpha[r] = -(m + logf(s));
}

// ---------------- generic [M,K]@[K,128] GEMM, 64-row tile (R10-verified) ----------------
template<int EPI>
__global__ void __launch_bounds__(256) gemm128_kernel(
    const float* __restrict__ A1, const float* __restrict__ A2,
    const float* __restrict__ W,  const float* __restrict__ bias,
    const float* __restrict__ g,  const float* __restrict__ bet,
    float* __restrict__ out, int K)
{
    __shared__ __align__(16) float As[32*65];
    __shared__ __align__(16) float Ws[32*128];
    int tid = threadIdx.x;
    int tx = tid & 15, ty = tid >> 4;
    int row0 = blockIdx.x * 64;

    ull acc[4][4];
    #pragma unroll
    for (int r = 0; r < 4; r++)
        #pragma unroll
        for (int j = 0; j < 4; j++) acc[r][j] = 0ULL;

    int nch = K >> 5;
    for (int cc = 0; cc < nch; cc++){
        int kg = cc << 5;
        const float* Asrc = (kg < 128) ? A1 : A2;
        int koff = (kg < 128) ? kg : kg - 128;
        __syncthreads();
        #pragma unroll
        for (int i = 0; i < 8; i++){
            int e = tid + i*256;
            int m = e >> 5, k = e & 31;
            As[k*65 + m] = Asrc[(row0 + m)*HD + koff + k];
        }
        #pragma unroll
        for (int i = 0; i < 16; i++){
            int e = tid + i*256;
            Ws[e] = W[kg*HD + e];
        }
        __syncthreads();
        #pragma unroll
        for (int k = 0; k < 32; k++){
            ull wv[4];
            #pragma unroll
            for (int j = 0; j < 4; j++)
                wv[j] = *reinterpret_cast<const ull*>(&Ws[k*HD + 2*tx + 32*j]);
            #pragma unroll
            for (int r = 0; r < 4; r++){
                float a = As[k*65 + ty*4 + r];
                ull ad = pk2(a, a);
                #pragma unroll
                for (int j = 0; j < 4; j++) fma2(acc[r][j], ad, wv[j]);
            }
        }
    }

    float bv[8];
    #pragma unroll
    for (int j = 0; j < 4; j++){
        bv[2*j]   = bias[2*tx + 32*j];
        bv[2*j+1] = bias[2*tx + 32*j + 1];
    }
    #pragma unroll
    for (int r = 0; r < 4; r++){
        int row = row0 + ty*4 + r;
        float v[8];
        #pragma unroll
        for (int j = 0; j < 4; j++){
            float2 p = upk(acc[r][j]);
            v[2*j] = p.x + bv[2*j]; v[2*j+1] = p.y + bv[2*j+1];
        }
        if (EPI == 2){
            #pragma unroll
            for (int u = 0; u < 8; u++) v[u] = fmaxf(v[u], 0.f);
        }
        if (EPI == 3){
            float s = 0.f, s2 = 0.f;
            #pragma unroll
            for (int u = 0; u < 8; u++){ s += v[u]; s2 += v[u]*v[u]; }
            #pragma unroll
            for (int d = 1; d < 16; d <<= 1){
                s  += __shfl_xor_sync(0xffffffffu, s,  d);
                s2 += __shfl_xor_sync(0xffffffffu, s2, d);
            }
            float mu = s * (1.f/HD);
            float rs = rsqrtf(s2 * (1.f/HD) - mu*mu + LNEPS);
            #pragma unroll
            for (int j = 0; j < 4; j++){
                int c = 2*tx + 32*j;
                v[2*j]   = (v[2*j]   - mu) * rs * g[c]   + bet[c];
                v[2*j+1] = (v[2*j+1] - mu) * rs * g[c+1] + bet[c+1];
            }
        }
        #pragma unroll
        for (int j = 0; j < 4; j++){
            float2 p; p.x = v[2*j]; p.y = v[2*j+1];
            *reinterpret_cast<float2*>(&out[row*HD + 2*tx + 32*j]) = p;
        }
    }
}

// ---------------- merged message GEMM (R10-verified 64-row) ----------------
__global__ void __launch_bounds__(256) gemm_msg_kernel(
    const float* __restrict__ A,
    const float* __restrict__ WR, const float* __restrict__ WS,
    const float* __restrict__ bR,
    float* __restrict__ outR, float* __restrict__ outS)
{
    __shared__ __align__(16) float As[32*65];
    __shared__ __align__(16) float WsR[32*128];
    __shared__ __align__(16) float WsS[32*128];
    int tid = threadIdx.x;
    int tx = tid & 15, ty = tid >> 4;
    int row0 = blockIdx.x * 64;

    ull accR[4][4], accS[4][4];
    #pragma unroll
    for (int r = 0; r < 4; r++)
        #pragma unroll
        for (int j = 0; j < 4; j++){ accR[r][j] = 0ULL; accS[r][j] = 0ULL; }

    for (int cc = 0; cc < 4; cc++){
        int kg = cc << 5;
        __syncthreads();
        #pragma unroll
        for (int i = 0; i < 8; i++){
            int e = tid + i*256;
            int m = e >> 5, k = e & 31;
            As[k*65 + m] = A[(row0 + m)*HD + kg + k];
        }
        #pragma unroll
        for (int i = 0; i < 16; i++){
            int e = tid + i*256;
            WsR[e] = WR[kg*HD + e];
            WsS[e] = WS[kg*HD + e];
        }
        __syncthreads();
        #pragma unroll
        for (int k = 0; k < 32; k++){
            ull wvR[4], wvS[4];
            #pragma unroll
            for (int j = 0; j < 4; j++){
                wvR[j] = *reinterpret_cast<const ull*>(&WsR[k*HD + 2*tx + 32*j]);
                wvS[j] = *reinterpret_cast<const ull*>(&WsS[k*HD + 2*tx + 32*j]);
            }
            #pragma unroll
            for (int r = 0; r < 4; r++){
                float a = As[k*65 + ty*4 + r];
                ull ad = pk2(a, a);
                #pragma unroll
                for (int j = 0; j < 4; j++){
                    fma2(accR[r][j], ad, wvR[j]);
                    fma2(accS[r][j], ad, wvS[j]);
                }
            }
        }
    }

    float bv[8];
    #pragma unroll
    for (int j = 0; j < 4; j++){
        bv[2*j]   = bR[2*tx + 32*j];
        bv[2*j+1] = bR[2*tx + 32*j + 1];
    }
    #pragma unroll
    for (int r = 0; r < 4; r++){
        int row = row0 + ty*4 + r;
        #pragma unroll
        for (int j = 0; j < 4; j++){
            float2 pr = upk(accR[r][j]);
            pr.x += bv[2*j]; pr.y += bv[2*j+1];
            *reinterpret_cast<float2*>(&outR[row*HD + 2*tx + 32*j]) = pr;
            float2 ps = upk(accS[r][j]);
            *reinterpret_cast<float2*>(&outS[row*HD + 2*tx + 32*j]) = ps;
        }
    }
}

// ---------------- scatter via bf16 mma: part[z][b,n,h] = sum_c S[c][n]*emb[c][h] ----------------
// A = S^T [n][c] (row-major), B = emb [c][h] stored transposed EhiT[h][c] (col-major pairs).
__global__ void __launch_bounds__(256) scatter_mma_kernel(
    const float* __restrict__ xc, const float* __restrict__ pos,
    const float* __restrict__ alpha, const float* __restrict__ emb,
    float* __restrict__ part)
{
    __shared__ __align__(16) __nv_bfloat16 EhiT[128][36];
    __shared__ __align__(16) __nv_bfloat16 EloT[128][36];
    __shared__ __align__(16) __nv_bfloat16 ShiT[32][36];
    __shared__ __align__(16) __nv_bfloat16 SloT[32][36];
    __shared__ float spx[32], spy[32], spn[32];
    int tid = threadIdx.x, lane = tid & 31, w = tid >> 5;
    int b = blockIdx.y, n0 = blockIdx.x*32, z = blockIdx.z;
    int g = lane >> 2, q = lane & 3;
    int mt = w & 1;              // m-tile (16 nodes)
    int nbase = (w >> 1) * 32;   // this warp's 32 h-columns (4 n-tiles of 8)

    if (tid < 32){
        float2 p = reinterpret_cast<const float2*>(pos)[n0 + tid];
        spx[tid] = p.x; spy[tid] = p.y; spn[tid] = p.x*p.x + p.y*p.y;
    }
    float c_[4][4];
    #pragma unroll
    for (int t = 0; t < 4; t++)
        #pragma unroll
        for (int u = 0; u < 4; u++) c_[t][u] = 0.f;

    int cbeg = z * (NCPT/KSPLIT);
    int cend = cbeg + (NCPT/KSPLIT);
    for (int cc = cbeg; cc < cend; cc += 32){
        __syncthreads();
        // fill E^T (emb hi/lo)
        #pragma unroll
        for (int i = 0; i < 16; i++){
            int e = tid + i*256;
            int c = e >> 7, h = e & 127;
            float v = emb[(b*NCPT + cc + c)*HD + h];
            __nv_bfloat16 hi, lo; split_bf16(v, hi, lo);
            EhiT[h][c] = hi; EloT[h][c] = lo;
        }
        // fill S^T (scores hi/lo)
        #pragma unroll
        for (int i = 0; i < 4; i++){
            int e = tid + i*256;
            int c = e >> 5, nl = e & 31;
            int crow = b*NCPT + cc + c;
            float2 x = reinterpret_cast<const float2*>(xc)[crow];
            float sc = __expf(2.f*(x.x*spx[nl] + x.y*spy[nl]) - spn[nl] + alpha[crow]);
            __nv_bfloat16 hi, lo; split_bf16(sc, hi, lo);
            ShiT[nl][c] = hi; SloT[nl][c] = lo;
        }
        __syncthreads();
        #pragma unroll
        for (int kk = 0; kk < 32; kk += 16){
            int ar = mt*16;
            int col = kk + 2*q;
            uint32 ah0 = *reinterpret_cast<const uint32*>(&ShiT[ar+g  ][col]);
            uint32 ah1 = *reinterpret_cast<const uint32*>(&ShiT[ar+g+8][col]);
            uint32 ah2 = *reinterpret_cast<const uint32*>(&ShiT[ar+g  ][col+8]);
            uint32 ah3 = *reinterpret_cast<const uint32*>(&ShiT[ar+g+8][col+8]);
            uint32 al0 = *reinterpret_cast<const uint32*>(&SloT[ar+g  ][col]);
            uint32 al1 = *reinterpret_cast<const uint32*>(&SloT[ar+g+8][col]);
            uint32 al2 = *reinterpret_cast<const uint32*>(&SloT[ar+g  ][col+8]);
            uint32 al3 = *reinterpret_cast<const uint32*>(&SloT[ar+g+8][col+8]);
            #pragma unroll
            for (int t = 0; t < 4; t++){
                int h = nbase + t*8 + g;
                uint32 bh0 = *reinterpret_cast<const uint32*>(&EhiT[h][col]);
                uint32 bh1 = *reinterpret_cast<const uint32*>(&EhiT[h][col+8]);
                uint32 bl0 = *reinterpret_cast<const uint32*>(&EloT[h][col]);
                uint32 bl1 = *reinterpret_cast<const uint32*>(&EloT[h][col+8]);
                mma16816(c_[t], ah0, ah1, ah2, ah3, bh0, bh1);
                mma16816(c_[t], ah0, ah1, ah2, ah3, bl0, bl1);
                mma16816(c_[t], al0, al1, al2, al3, bh0, bh1);
            }
        }
    }
    int zoff = z * (BATCH*NND*HD);
    #pragma unroll
    for (int t = 0; t < 4; t++){
        int h = nbase + t*8 + 2*q;
        int row0 = b*NND + n0 + mt*16 + g;
        float2 o0; o0.x = c_[t][0]; o0.y = c_[t][1];
        *reinterpret_cast<float2*>(&part[zoff + row0*HD + h]) = o0;
        float2 o1; o1.x = c_[t][2]; o1.y = c_[t][3];
        *reinterpret_cast<float2*>(&part[zoff + (row0+8)*HD + h]) = o1;
    }
}

// ---------------- reduce KSPLIT partials (fixed order -> deterministic) ----------------
__global__ void __launch_bounds__(256) reduceK_kernel(
    const float4* __restrict__ part, float4* __restrict__ dst)
{
    int i = blockIdx.x*256 + threadIdx.x;
    const int S = BATCH*NND*HD/4;
    float4 o = part[i];
    #pragma unroll
    for (int zz = 1; zz < KSPLIT; zz++){
        float4 a = part[i + zz*S];
        o.x += a.x; o.y += a.y; o.z += a.z; o.w += a.w;
    }
    dst[i] = o;
}

// ---------------- gatherz via bf16 mma: z[t][h] = sum_n S[t][n]*lat[n][h] ----------------
__global__ void __launch_bounds__(256) gatherz_mma_kernel(
    const float* __restrict__ xt, const float* __restrict__ pos,
    const float* __restrict__ alpha, const float* __restrict__ lat,
    float* __restrict__ z)
{
    __shared__ __align__(16) __nv_bfloat16 LhiT[128][36];
    __shared__ __align__(16) __nv_bfloat16 LloT[128][36];
    __shared__ __align__(16) __nv_bfloat16 ShiT[64][36];
    __shared__ __align__(16) __nv_bfloat16 SloT[64][36];
    __shared__ float sx0[64], sx1[64], sal[64];
    int tid = threadIdx.x, lane = tid & 31, w = tid >> 5;
    int b = blockIdx.y, t0 = blockIdx.x*64;
    int g = lane >> 2, q = lane & 3;
    int mt = w >> 1;             // m-tile (16 targets)
    int nbase = (w & 1) * 64;    // this warp's 64 h-columns (8 n-tiles of 8)

    if (tid < 64){
        int trow = b*NTPT + t0 + tid;
        float2 x = reinterpret_cast<const float2*>(xt)[trow];
        sx0[tid] = x.x; sx1[tid] = x.y; sal[tid] = alpha[trow];
    }
    float c_[8][4];
    #pragma unroll
    for (int t = 0; t < 8; t++)
        #pragma unroll
        for (int u = 0; u < 4; u++) c_[t][u] = 0.f;

    for (int nn = 0; nn < NND; nn += 32){
        __syncthreads();
        // fill lat^T (hi/lo)
        #pragma unroll
        for (int i = 0; i < 16; i++){
            int e = tid + i*256;
            int c = e >> 7, h = e & 127;
            float v = lat[(b*NND + nn + c)*HD + h];
            __nv_bfloat16 hi, lo; split_bf16(v, hi, lo);
            LhiT[h][c] = hi; LloT[h][c] = lo;
        }
        // fill scores S[t][n-local] (hi/lo)
        #pragma unroll
        for (int i = 0; i < 8; i++){
            int e = tid + i*256;
            int nl = e >> 6, tl = e & 63;
            float2 p = reinterpret_cast<const float2*>(pos)[nn + nl];
            float sc = __expf(2.f*(sx0[tl]*p.x + sx1[tl]*p.y)
                              - (p.x*p.x + p.y*p.y) + sal[tl]);
            __nv_bfloat16 hi, lo; split_bf16(sc, hi, lo);
            ShiT[tl][nl] = hi; SloT[tl][nl] = lo;
        }
        __syncthreads();
        #pragma unroll
        for (int kk = 0; kk < 32; kk += 16){
            int ar = mt*16;
            int col = kk + 2*q;
            uint32 ah0 = *reinterpret_cast<const uint32*>(&ShiT[ar+g  ][col]);
            uint32 ah1 = *reinterpret_cast<const uint32*>(&ShiT[ar+g+8][col]);
            uint32 ah2 = *reinterpret_cast<const uint32*>(&ShiT[ar+g  ][col+8]);
            uint32 ah3 = *reinterpret_cast<const uint32*>(&ShiT[ar+g+8][col+8]);
            uint32 al0 = *reinterpret_cast<const uint32*>(&SloT[ar+g  ][col]);
            uint32 al1 = *reinterpret_cast<const uint32*>(&SloT[ar+g+8][col]);
            uint32 al2 = *reinterpret_cast<const uint32*>(&SloT[ar+g  ][col+8]);
            uint32 al3 = *reinterpret_cast<const uint32*>(&SloT[ar+g+8][col+8]);
            #pragma unroll
            for (int t = 0; t < 8; t++){
                int h = nbase + t*8 + g;
                uint32 bh0 = *reinterpret_cast<const uint32*>(&LhiT[h][col]);
                uint32 bh1 = *reinterpret_cast<const uint32*>(&LhiT[h][col+8]);
                uint32 bl0 = *reinterpret_cast<const uint32*>(&LloT[h][col]);
                uint32 bl1 = *reinterpret_cast<const uint32*>(&LloT[h][col+8]);
                mma16816(c_[t], ah0, ah1, ah2, ah3, bh0, bh1);
                mma16816(c_[t], ah0, ah1, ah2, ah3, bl0, bl1);
                mma16816(c_[t], al0, al1, al2, al3, bh0, bh1);
            }
        }
    }
    #pragma unroll
    for (int t = 0; t < 8; t++){
        int h = nbase + t*8 + 2*q;
        int row0 = b*NTPT + t0 + mt*16 + g;
        float2 o0; o0.x = c_[t][0]; o0.y = c_[t][1];
        *reinterpret_cast<float2*>(&z[row0*HD + h]) = o0;
        float2 o1; o1.x = c_[t][2]; o1.y = c_[t][3];
        *reinterpret_cast<float2*>(&z[(row0+8)*HD + h]) = o1;
    }
}

// ---------------- CSR build (deterministic after per-bucket sort) ----------------
__global__ void csr_zero_kernel(int* cnt){ cnt[blockIdx.x*256 + threadIdx.x] = 0; }
__global__ void csr_count_kernel(const int* __restrict__ recv, int* cnt){
    int e = blockIdx.x*256 + threadIdx.x;
    atomicAdd(&cnt[recv[e]], 1);
}
__global__ void csr_scan_kernel(const int* __restrict__ cnt, int* off, int* cur){
    __shared__ int s[NND];
    int t = threadIdx.x;
    s[t] = cnt[t]; __syncthreads();
    for (int d = 1; d < NND; d <<= 1){
        int v = (t >= d) ? s[t-d] : 0;
        __syncthreads();
        s[t] += v;
        __syncthreads();
    }
    int excl = s[t] - cnt[t];
    off[t] = excl; cur[t] = excl;
    if (t == NND-1) off[NND] = s[NND-1];
}
__global__ void csr_fill_kernel(const int* __restrict__ recv, int* cur, int* csr){
    int e = blockIdx.x*256 + threadIdx.x;
    int slot = atomicAdd(&cur[recv[e]], 1);
    csr[slot] = e;
}
__global__ void csr_sort_kernel(const int* __restrict__ off, int* csr){
    int n = blockIdx.x*256 + threadIdx.x;
    if (n >= NND) return;
    int s0 = off[n], s1 = off[n+1];
    for (int i = s0+1; i < s1; i++){
        int v = csr[i], j = i-1;
        while (j >= s0 && csr[j] > v){ csr[j+1] = csr[j]; j--; }
        csr[j+1] = v;
    }
}

// ---------------- per (b,node) in-edge accumulation with edge LayerNorm ----------------
__global__ void __launch_bounds__(256) inbox_kernel(
    const float* __restrict__ NR, const float* __restrict__ NS,
    const float* __restrict__ lg, const float* __restrict__ lb,
    const int* __restrict__ senders, const int* __restrict__ off,
    const int* __restrict__ csr, float* __restrict__ inbox)
{
    int w = (blockIdx.x*256 + threadIdx.x) >> 5;
    int lane = threadIdx.x & 31;
    int b = w / NND, n = w - b*NND;
    int c0 = lane*4;
    float4 nr = *reinterpret_cast<const float4*>(&NR[(b*NND+n)*HD + c0]);
    float4 gl = *reinterpret_cast<const float4*>(&lg[c0]);
    float4 bl = *reinterpret_cast<const float4*>(&lb[c0]);
    float a0=0.f, a1=0.f, a2=0.f, a3=0.f;
    int s0 = off[n], s1 = off[n+1];
    for (int i = s0; i < s1; i++){
        int e = csr[i];
        int s = senders[e];
        float4 ns = *reinterpret_cast<const float4*>(&NS[(b*NND+s)*HD + c0]);
        float v0 = nr.x+ns.x, v1 = nr.y+ns.y, v2 = nr.z+ns.z, v3 = nr.w+ns.w;
        float sm = v0+v1+v2+v3;
        float sq = v0*v0+v1*v1+v2*v2+v3*v3;
        #pragma unroll
        for (int d = 1; d < 32; d <<= 1){
            sm += __shfl_xor_sync(0xffffffffu, sm, d);
            sq += __shfl_xor_sync(0xffffffffu, sq, d);
        }
        float mu = sm*(1.f/HD);
        float rs = rsqrtf(sq*(1.f/HD) - mu*mu + LNEPS);
        a0 += (v0-mu)*rs*gl.x + bl.x;
        a1 += (v1-mu)*rs*gl.y + bl.y;
        a2 += (v2-mu)*rs*gl.z + bl.z;
        a3 += (v3-mu)*rs*gl.w + bl.w;
    }
    float4 o; o.x=a0; o.y=a1; o.z=a2; o.w=a3;
    *reinterpret_cast<float4*>(&inbox[(b*NND+n)*HD + c0]) = o;
}

// ---------------- final decoder layer [.,128]@[128,3] (warp per row) ----------------
__global__ void __launch_bounds__(256) dec_final_kernel(
    const float* __restrict__ Hh, const float* __restrict__ W2,
    const float* __restrict__ b2, float* __restrict__ out)
{
    int w = (blockIdx.x*256 + threadIdx.x) >> 5;
    int lane = threadIdx.x & 31;
    float4 h = *reinterpret_cast<const float4*>(&Hh[w*HD + lane*4]);
    int k0 = lane*4;
    float a[3];
    #pragma unroll
    for (int j = 0; j < 3; j++)
        a[j] = h.x*W2[k0*3+j] + h.y*W2[(k0+1)*3+j] + h.z*W2[(k0+2)*3+j] + h.w*W2[(k0+3)*3+j];
    #pragma unroll
    for (int d = 1; d < 32; d <<= 1){
        #pragma unroll
        for (int j = 0; j < 3; j++) a[j] += __shfl_xor_sync(0xffffffffu, a[j], d);
    }
    if (lane == 0){
        #pragma unroll
        for (int j = 0; j < 3; j++) out[w*3 + j] = a[j] + b2[j];
    }
}

// ---------------- host ----------------
extern "C" void kernel_launch(void* const* d_in, const int* in_sizes, int n_in,
                              void* d_out, int out_size)
{
    const float* xc   = (const float*)d_in[0];
    const float* yc   = (const float*)d_in[1];
    const float* xt   = (const float*)d_in[2];
    const float* pos  = (const float*)d_in[3];
    const float* enc_W0 = (const float*)d_in[4];  const float* enc_b0 = (const float*)d_in[5];
    const float* enc_W1 = (const float*)d_in[6];  const float* enc_b1 = (const float*)d_in[7];
    const float* enc_W2 = (const float*)d_in[8];  const float* enc_b2 = (const float*)d_in[9];
    const float* qenc_W0 = (const float*)d_in[10]; const float* qenc_b0 = (const float*)d_in[11];
    const float* qenc_W1 = (const float*)d_in[12]; const float* qenc_b1 = (const float*)d_in[13];
    const float* qenc_W2 = (const float*)d_in[14]; const float* qenc_b2 = (const float*)d_in[15];
    const float* dec_W0 = (const float*)d_in[16]; const float* dec_b0 = (const float*)d_in[17];
    const float* dec_W1 = (const float*)d_in[18]; const float* dec_b1 = (const float*)d_in[19];
    const float* dec_W2 = (const float*)d_in[20]; const float* dec_b2 = (const float*)d_in[21];
    const float* msg_W  = (const float*)d_in[22]; const float* msg_b  = (const float*)d_in[23];
    const float* ln1_g  = (const float*)d_in[24]; const float* ln1_b  = (const float*)d_in[25];
    const float* node_W = (const float*)d_in[26]; const float* node_b = (const float*)d_in[27];
    const float* ln2_g  = (const float*)d_in[28]; const float* ln2_b  = (const float*)d_in[29];
    const int* senders   = (const int*)d_in[30];
    const int* receivers = (const int*)d_in[31];
    float* out = (float*)d_out;

    void* p;
    cudaGetSymbolAddress(&p, g_tmpA); float* tmpA = (float*)p;
    cudaGetSymbolAddress(&p, g_tmpB); float* tmpB = (float*)p;
    cudaGetSymbolAddress(&p, g_emb);  float* emb  = (float*)p;
    cudaGetSymbolAddress(&p, g_q);    float* q    = (float*)p;
    cudaGetSymbolAddress(&p, g_z);    float* z    = (float*)p;
    cudaGetSymbolAddress(&p, g_latA); float* latA = (float*)p;
    cudaGetSymbolAddress(&p, g_latB); float* latB = (float*)p;
    cudaGetSymbolAddress(&p, g_NR);   float* NR   = (float*)p;
    cudaGetSymbolAddress(&p, g_NS);   float* NS   = (float*)p;
    cudaGetSymbolAddress(&p, g_inb);  float* inb  = (float*)p;
    cudaGetSymbolAddress(&p, g_alC);  float* alC  = (float*)p;
    cudaGetSymbolAddress(&p, g_alT);  float* alT  = (float*)p;
    cudaGetSymbolAddress(&p, g_cnt);  int* cnt = (int*)p;
    cudaGetSymbolAddress(&p, g_cur);  int* cur = (int*)p;
    cudaGetSymbolAddress(&p, g_off);  int* off = (int*)p;
    cudaGetSymbolAddress(&p, g_csr);  int* csr = (int*)p;

    const int rows_c = BATCH*NCPT;      // 32768
    const int rows_t = BATCH*NTPT;      // 32768
    const int rows_n = BATCH*NND;       // 8192

    // --- encoder MLP on context points (launches 0-2) ---
    mlp_l1_kernel<<<rows_c, HD>>>(xc, 2, yc, 3, enc_W0, enc_b0, tmpA);
    gemm128_kernel<2><<<rows_c/64, 256>>>(tmpA, tmpA, enc_W1, enc_b1, 0, 0, tmpB, 128);
    gemm128_kernel<1><<<rows_c/64, 256>>>(tmpB, tmpB, enc_W2, enc_b2, 0, 0, emb, 128);

    // --- softmax normalizers (3), csr_zero (4), scatter_mma (5, ncu target) ---
    alpha2_kernel<<<(rows_c+rows_t)/8, 256>>>(xc, xt, pos, alC, alT);
    csr_zero_kernel<<<NND/256, 256>>>(cnt);
    scatter_mma_kernel<<<dim3(NND/32, BATCH, KSPLIT), 256>>>(xc, pos, alC, emb, tmpA);
    reduceK_kernel<<<rows_n*HD/4/256, 256>>>((const float4*)tmpA, (float4*)latA);

    // --- rest of CSR build (deterministic) ---
    csr_count_kernel<<<NE/256, 256>>>(receivers, cnt);
    csr_scan_kernel<<<1, NND>>>(cnt, off, cur);
    csr_fill_kernel<<<NE/256, 256>>>(receivers, cur, csr);
    csr_sort_kernel<<<NND/256, 256>>>(off, csr);

    // --- 4 shared-weight graph blocks (R10-verified 64-row kernels) ---
    float* curL = latA; float* othL = latB;
    for (int step = 0; step < 4; step++){
        gemm_msg_kernel<<<rows_n/64, 256>>>(curL, msg_W, msg_W + 128*HD, msg_b, NR, NS);
        inbox_kernel<<<rows_n/8, 256>>>(NR, NS, ln1_g, ln1_b, senders, off, csr, inb);
        gemm128_kernel<3><<<rows_n/64, 256>>>(curL, inb, node_W, node_b, ln2_g, ln2_b, othL, 256);
        float* t = curL; curL = othL; othL = t;
    }

    // --- query encoder ---
    mlp_l1_kernel<<<rows_t, HD>>>(xt, 2, xt, 0, qenc_W0, qenc_b0, tmpA);
    gemm128_kernel<2><<<rows_t/64, 256>>>(tmpA, tmpA, qenc_W1, qenc_b1, 0, 0, tmpB, 128);
    gemm128_kernel<1><<<rows_t/64, 256>>>(tmpB, tmpB, qenc_W2, qenc_b2, 0, 0, q, 128);

    // --- readout z (bf16 mma) ---
    gatherz_mma_kernel<<<dim3(NTPT/64, BATCH), 256>>>(xt, pos, alT, curL, z);

    // --- decoder ---
    gemm128_kernel<2><<<rows_t/64, 256>>>(z, q, dec_W0, dec_b0, 0, 0, tmpA, 256);
    gemm128_kernel<2><<<rows_t/64, 256>>>(tmpA, tmpA, dec_W1, dec_b1, 0, 0, tmpB, 128);
    dec_final_kernel<<<rows_t/8, 256>>>(tmpB, dec_W2, dec_b2, out);
}